// round 2
// baseline (speedup 1.0000x reference)
#include <cuda_runtime.h>

// Problem dims
#define B_BATCH 8
#define L_SEQ   256
#define D1      512
#define D2      512
#define KOUT    64
#define M1      (B_BATCH * L_SEQ)   // 2048 rows (b,i)

// Scratch: tmp[(b,i), k, q]  = 2048 * 64 * 512 floats = 256 MiB
// (__device__ global array is the sanctioned alloc-free scratch mechanism)
__device__ float g_tmp[(size_t)M1 * KOUT * D2];

// ---------------------------------------------------------------------------
// Kernel 1:  for each k:  Tmp_k = X1 @ W_k
//   X1: [2048, 512] row-major
//   W_k: [512, 512] row-major (p x q)
//   write tmp[(m)*KOUT*D2 + k*D2 + n]
// Tile: 128x128 per block, BK=16, 256 threads, 8x8 per thread.
// ---------------------------------------------------------------------------
__global__ __launch_bounds__(256) void gemm1_kernel(
    const float* __restrict__ X1, const float* __restrict__ W)
{
    const int m0 = blockIdx.x * 128;
    const int n0 = blockIdx.y * 128;
    const int k  = blockIdx.z;
    const float* __restrict__ Bmat = W + (size_t)k * D1 * D2;

    __shared__ float As[16][128];  // transposed: As[q][m]
    __shared__ float Bs[16][128];  // Bs[q][n]

    const int tid  = threadIdx.x;
    const int rowg = (tid >> 4) * 8;   // m sub-tile (row group)
    const int colg = (tid & 15) * 8;   // n sub-tile (col group)

    float acc[8][8];
#pragma unroll
    for (int i = 0; i < 8; i++)
#pragma unroll
        for (int j = 0; j < 8; j++) acc[i][j] = 0.0f;

    for (int q0 = 0; q0 < D1; q0 += 16) {
        // Load A tile 128x16 (512 float4), transpose into As[q][m]
#pragma unroll
        for (int rep = 0; rep < 2; rep++) {
            int id = tid + rep * 256;
            int r  = id >> 2;            // row 0..127
            int c4 = (id & 3) * 4;       // q offset 0,4,8,12
            float4 v = *reinterpret_cast<const float4*>(
                &X1[(size_t)(m0 + r) * D1 + q0 + c4]);
            As[c4 + 0][r] = v.x;
            As[c4 + 1][r] = v.y;
            As[c4 + 2][r] = v.z;
            As[c4 + 3][r] = v.w;
        }
        // Load B tile 16x128 (512 float4), direct
#pragma unroll
        for (int rep = 0; rep < 2; rep++) {
            int id = tid + rep * 256;
            int r  = id >> 5;            // q row 0..15
            int c4 = (id & 31) * 4;      // n offset
            *reinterpret_cast<float4*>(&Bs[r][c4]) =
                *reinterpret_cast<const float4*>(
                    &Bmat[(size_t)(q0 + r) * D2 + n0 + c4]);
        }
        __syncthreads();

#pragma unroll
        for (int kk = 0; kk < 16; kk++) {
            float a[8], b[8];
            *reinterpret_cast<float4*>(&a[0]) = *reinterpret_cast<float4*>(&As[kk][rowg]);
            *reinterpret_cast<float4*>(&a[4]) = *reinterpret_cast<float4*>(&As[kk][rowg + 4]);
            *reinterpret_cast<float4*>(&b[0]) = *reinterpret_cast<float4*>(&Bs[kk][colg]);
            *reinterpret_cast<float4*>(&b[4]) = *reinterpret_cast<float4*>(&Bs[kk][colg + 4]);
#pragma unroll
            for (int i = 0; i < 8; i++)
#pragma unroll
                for (int j = 0; j < 8; j++)
                    acc[i][j] += a[i] * b[j];
        }
        __syncthreads();
    }

    // Epilogue: tmp[(m)*KOUT*D2 + k*D2 + n], rows contiguous in n
#pragma unroll
    for (int i = 0; i < 8; i++) {
        size_t base = (size_t)(m0 + rowg + i) * (KOUT * D2) + (size_t)k * D2 + n0 + colg;
        *reinterpret_cast<float4*>(&g_tmp[base]) =
            make_float4(acc[i][0], acc[i][1], acc[i][2], acc[i][3]);
        *reinterpret_cast<float4*>(&g_tmp[base + 4]) =
            make_float4(acc[i][4], acc[i][5], acc[i][6], acc[i][7]);
    }
}

// ---------------------------------------------------------------------------
// Kernel 2: one block per (b,i):  C[j,k] = sum_q X2[b][j,q] * tmp[b,i,k,q] + bias[k]
//   Tile: full 256(j) x 64(k), QC=16, 256 threads, 8x8 per thread (j x k).
//   Output [256,64] tile is fully contiguous -> coalesced stores.
// ---------------------------------------------------------------------------
__global__ __launch_bounds__(256) void gemm2_kernel(
    const float* __restrict__ X2, const float* __restrict__ bias,
    float* __restrict__ out)
{
    const int bi = blockIdx.x;           // b*L + i
    const int b  = bi >> 8;
    const float* __restrict__ x2b = X2 + (size_t)b * L_SEQ * D2;
    const float* __restrict__ tb  = g_tmp + (size_t)bi * KOUT * D2;

    __shared__ float X2s[16][256];   // X2s[q][j]
    __shared__ float Ts[16][64];     // Ts[q][k]

    const int tid = threadIdx.x;
    const int k0  = (tid & 7) * 8;    // k group (fast -> coalesced stores)
    const int j0  = (tid >> 3) * 8;   // j group

    float acc[8][8];                  // [j][k]
#pragma unroll
    for (int j = 0; j < 8; j++)
#pragma unroll
        for (int kk = 0; kk < 8; kk++) acc[j][kk] = 0.0f;

    for (int q0 = 0; q0 < D2; q0 += 16) {
        // Load X2 chunk 256x16 (1024 float4), transpose into X2s[q][j]
#pragma unroll
        for (int rep = 0; rep < 4; rep++) {
            int id = tid + rep * 256;
            int r  = id >> 2;          // j 0..255
            int c4 = (id & 3) * 4;
            float4 v = *reinterpret_cast<const float4*>(
                &x2b[(size_t)r * D2 + q0 + c4]);
            X2s[c4 + 0][r] = v.x;
            X2s[c4 + 1][r] = v.y;
            X2s[c4 + 2][r] = v.z;
            X2s[c4 + 3][r] = v.w;
        }
        // Load T chunk 64x16 (256 float4), transpose into Ts[q][k]
        {
            int id = tid;
            int r  = id >> 2;          // k 0..63
            int c4 = (id & 3) * 4;
            float4 v = *reinterpret_cast<const float4*>(
                &tb[(size_t)r * D2 + q0 + c4]);
            Ts[c4 + 0][r] = v.x;
            Ts[c4 + 1][r] = v.y;
            Ts[c4 + 2][r] = v.z;
            Ts[c4 + 3][r] = v.w;
        }
        __syncthreads();

#pragma unroll
        for (int qq = 0; qq < 16; qq++) {
            float a[8], bk[8];
            *reinterpret_cast<float4*>(&a[0])  = *reinterpret_cast<float4*>(&X2s[qq][j0]);
            *reinterpret_cast<float4*>(&a[4])  = *reinterpret_cast<float4*>(&X2s[qq][j0 + 4]);
            *reinterpret_cast<float4*>(&bk[0]) = *reinterpret_cast<float4*>(&Ts[qq][k0]);
            *reinterpret_cast<float4*>(&bk[4]) = *reinterpret_cast<float4*>(&Ts[qq][k0 + 4]);
#pragma unroll
            for (int j = 0; j < 8; j++)
#pragma unroll
                for (int kk = 0; kk < 8; kk++)
                    acc[j][kk] += a[j] * bk[kk];
        }
        __syncthreads();
    }

    // Epilogue: out[((bi)*256 + j)*64 + k] + bias[k]
    float bv[8];
    *reinterpret_cast<float4*>(&bv[0]) = *reinterpret_cast<const float4*>(&bias[k0]);
    *reinterpret_cast<float4*>(&bv[4]) = *reinterpret_cast<const float4*>(&bias[k0 + 4]);
#pragma unroll
    for (int j = 0; j < 8; j++) {
        size_t base = ((size_t)bi * L_SEQ + (j0 + j)) * KOUT + k0;
        *reinterpret_cast<float4*>(&out[base]) =
            make_float4(acc[j][0] + bv[0], acc[j][1] + bv[1],
                        acc[j][2] + bv[2], acc[j][3] + bv[3]);
        *reinterpret_cast<float4*>(&out[base + 4]) =
            make_float4(acc[j][4] + bv[4], acc[j][5] + bv[5],
                        acc[j][6] + bv[6], acc[j][7] + bv[7]);
    }
}

extern "C" void kernel_launch(void* const* d_in, const int* in_sizes, int n_in,
                              void* d_out, int out_size)
{
    const float* x1   = (const float*)d_in[0];   // [8,256,512]
    const float* x2   = (const float*)d_in[1];   // [8,256,512]
    const float* w    = (const float*)d_in[2];   // [64,512,512]
    const float* bias = (const float*)d_in[3];   // [64]
    float* out = (float*)d_out;                  // [8,256,256,64]

    dim3 grid1(M1 / 128, D2 / 128, KOUT);        // 16 x 4 x 64
    gemm1_kernel<<<grid1, 256>>>(x1, w);

    gemm2_kernel<<<M1, 256>>>(x2, bias, out);
}

// round 6
// speedup vs baseline: 2.9648x; 2.9648x over previous
#include <cuda_runtime.h>
#include <cuda_bf16.h>
#include <cstdint>

// ---------------------------------------------------------------------------
// Problem dims
// ---------------------------------------------------------------------------
#define B_BATCH 8
#define L_SEQ   256
#define D1      512
#define D2      512
#define KOUT    64
#define M1      (B_BATCH * L_SEQ)   // 2048 rows (b,i)

// ---------------------------------------------------------------------------
// Helpers (sm_80-era ISA only: ldmatrix / mma.sync / cp.async — NO tcgen05,
// the harness PTX target is sm_103 (no 'a'), which rejects arch-accel features)
// ---------------------------------------------------------------------------
__device__ __forceinline__ uint32_t smem_u32(const void* p) {
    uint32_t a;
    asm("{ .reg .u64 t; cvta.to.shared.u64 t, %1; cvt.u32.u64 %0, t; }"
        : "=r"(a) : "l"(p));
    return a;
}

__device__ __forceinline__ uint32_t swz(uint32_t off) {   // SW128 swizzle
    return off ^ ((off >> 3) & 0x70);
}

#define LDSM_X4(r0, r1, r2, r3, addr) \
    asm volatile("ldmatrix.sync.aligned.m8n8.x4.shared.b16 {%0,%1,%2,%3}, [%4];" \
        : "=r"(r0), "=r"(r1), "=r"(r2), "=r"(r3) : "r"(addr))

#define CP_ASYNC16(smem_addr, gptr) \
    asm volatile("cp.async.cg.shared.global [%0], [%1], 16;" \
        :: "r"(smem_addr), "l"(gptr))

#define CP_COMMIT()  asm volatile("cp.async.commit_group;" ::: "memory")
#define CP_WAIT(N)   asm volatile("cp.async.wait_group %0;" :: "n"(N) : "memory")

__device__ __forceinline__ void mma_bf16(float* c, const uint32_t* a, const uint32_t* b) {
    asm volatile(
        "mma.sync.aligned.m16n8k16.row.col.f32.bf16.bf16.f32 "
        "{%0,%1,%2,%3}, {%4,%5,%6,%7}, {%8,%9}, {%0,%1,%2,%3};"
        : "+f"(c[0]), "+f"(c[1]), "+f"(c[2]), "+f"(c[3])
        : "r"(a[0]), "r"(a[1]), "r"(a[2]), "r"(a[3]), "r"(b[0]), "r"(b[1]));
}

__device__ __forceinline__ uint32_t pack2bf(float a, float b) {
    __nv_bfloat162 t = __floats2bfloat162_rn(a, b);
    return *reinterpret_cast<uint32_t*>(&t);
}

// ---------------------------------------------------------------------------
// Scratch (__device__ globals = sanctioned alloc-free scratch)
// ---------------------------------------------------------------------------
__device__ __align__(256) __nv_bfloat16 g_a1h[(size_t)M1 * D1];
__device__ __align__(256) __nv_bfloat16 g_a1l[(size_t)M1 * D1];
__device__ __align__(256) __nv_bfloat16 g_x2h[(size_t)M1 * D2];
__device__ __align__(256) __nv_bfloat16 g_x2l[(size_t)M1 * D2];
__device__ __align__(256) __nv_bfloat16 g_wth[(size_t)KOUT * D2 * D1];  // W^T hi [k][q][p]
__device__ __align__(256) __nv_bfloat16 g_wtl[(size_t)KOUT * D2 * D1];  // W^T lo
__device__ __align__(256) __nv_bfloat16 g_th[(size_t)M1 * KOUT * D2];   // tmp hi [m][k][q]
__device__ __align__(256) __nv_bfloat16 g_tl[(size_t)M1 * KOUT * D2];   // tmp lo

// ---------------------------------------------------------------------------
// Conversion kernels
// ---------------------------------------------------------------------------
__global__ __launch_bounds__(256) void cvt_split_kernel(
    const float* __restrict__ in, __nv_bfloat16* __restrict__ hi,
    __nv_bfloat16* __restrict__ lo, int n4)
{
    int i = blockIdx.x * 256 + threadIdx.x;
    if (i >= n4) return;
    float4 v = reinterpret_cast<const float4*>(in)[i];
    __nv_bfloat16 h0 = __float2bfloat16(v.x);
    __nv_bfloat16 h1 = __float2bfloat16(v.y);
    __nv_bfloat16 h2 = __float2bfloat16(v.z);
    __nv_bfloat16 h3 = __float2bfloat16(v.w);
    reinterpret_cast<__nv_bfloat162*>(hi)[2 * i]     = __halves2bfloat162(h0, h1);
    reinterpret_cast<__nv_bfloat162*>(hi)[2 * i + 1] = __halves2bfloat162(h2, h3);
    reinterpret_cast<__nv_bfloat162*>(lo)[2 * i] = __halves2bfloat162(
        __float2bfloat16(v.x - __bfloat162float(h0)),
        __float2bfloat16(v.y - __bfloat162float(h1)));
    reinterpret_cast<__nv_bfloat162*>(lo)[2 * i + 1] = __halves2bfloat162(
        __float2bfloat16(v.z - __bfloat162float(h2)),
        __float2bfloat16(v.w - __bfloat162float(h3)));
}

// W[k][p][q] -> Wt[k][q][p], bf16 hi/lo.  grid (16,16,64), block (32,8)
__global__ void cvt_w_kernel(const float* __restrict__ W)
{
    __shared__ float t[32][33];
    int k  = blockIdx.z;
    int q0 = blockIdx.x * 32;
    int p0 = blockIdx.y * 32;
    const float* Wk = W + (size_t)k * D1 * D2;
    int tx = threadIdx.x, ty = threadIdx.y;
#pragma unroll
    for (int i = 0; i < 4; i++)
        t[ty + 8 * i][tx] = Wk[(size_t)(p0 + ty + 8 * i) * D2 + q0 + tx];
    __syncthreads();
#pragma unroll
    for (int i = 0; i < 4; i++) {
        float v = t[tx][ty + 8 * i];
        size_t o = (size_t)k * D2 * D1 + (size_t)(q0 + ty + 8 * i) * D1 + p0 + tx;
        __nv_bfloat16 h = __float2bfloat16(v);
        g_wth[o] = h;
        g_wtl[o] = __float2bfloat16(v - __bfloat162float(h));
    }
}

// ---------------------------------------------------------------------------
// Async tile copy: ROWS rows x 64 bf16 (128B rows), gmem pitch 512 elems,
// into SW128-swizzled SMEM.
// ---------------------------------------------------------------------------
template <int ROWS>
__device__ __forceinline__ void tile_cp(
    const __nv_bfloat16* __restrict__ g, uint32_t s, int tid)
{
#pragma unroll
    for (int idx = tid; idx < ROWS * 8; idx += 256) {
        int row = idx >> 3, u = idx & 7;
        CP_ASYNC16(s + swz((uint32_t)(row * 128 + u * 16)),
                   g + (size_t)row * 512 + u * 8);
    }
}

// ---------------------------------------------------------------------------
// GEMM1: tmp[m, kb, q] = sum_p X1[m,p] * W[kb,p,q]   (3-pass bf16 hi/lo)
//   grid (16, 4, 64), block 256 (8 warps).  Block tile 128(m) x 128(q), K=512
//   in 8 chunks of 64, double-buffered cp.async.
// SMEM: slot s at 1024 + s*64K:  Ah(16K) Al(16K) Bh(16K) Bl(16K).
// Epilogue stages hi/lo bf16 through padded SMEM (reuses tile area).
// ---------------------------------------------------------------------------
#define G1_SLOT 65536
#define G1_SMEM (1024 + 2 * G1_SLOT)

__global__ __launch_bounds__(256) void gemm1_mma(void)
{
    extern __shared__ char smem[];
    uint32_t sb = smem_u32(smem);
    const int tid = threadIdx.x, wid = tid >> 5, lane = tid & 31;
    const int m0 = blockIdx.x * 128, n0 = blockIdx.y * 128, kb = blockIdx.z;
    const int wm = wid & 3, wn = wid >> 2;       // warp tile 32(m) x 64(n)

    const __nv_bfloat16* Ah = g_a1h + (size_t)m0 * D1;
    const __nv_bfloat16* Al = g_a1l + (size_t)m0 * D1;
    const __nv_bfloat16* Bh = g_wth + ((size_t)kb * D2 + n0) * D1;
    const __nv_bfloat16* Bl = g_wtl + ((size_t)kb * D2 + n0) * D1;

    float c[2][8][4];
#pragma unroll
    for (int i = 0; i < 2; i++)
#pragma unroll
        for (int j = 0; j < 8; j++)
#pragma unroll
            for (int e = 0; e < 4; e++) c[i][j][e] = 0.0f;

    // ldmatrix per-lane geometry
    const int a_r = lane & 15, a_c = (lane >> 4) * 8;
    const int b_r = ((lane >> 4) & 1) * 8 + (lane & 7), b_c = ((lane >> 3) & 1) * 8;

    // prologue: chunk 0 -> slot 0
    {
        uint32_t tb = sb + 1024;
        tile_cp<128>(Ah, tb, tid);
        tile_cp<128>(Al, tb + 16384, tid);
        tile_cp<128>(Bh, tb + 32768, tid);
        tile_cp<128>(Bl, tb + 49152, tid);
        CP_COMMIT();
    }

#pragma unroll 1
    for (int ch = 0; ch < 8; ch++) {
        if (ch < 7) {
            int p0 = (ch + 1) * 64;
            uint32_t tb = sb + 1024 + ((ch + 1) & 1) * G1_SLOT;
            tile_cp<128>(Ah + p0, tb, tid);
            tile_cp<128>(Al + p0, tb + 16384, tid);
            tile_cp<128>(Bh + p0, tb + 32768, tid);
            tile_cp<128>(Bl + p0, tb + 49152, tid);
            CP_COMMIT();
            CP_WAIT(1);
        } else {
            CP_WAIT(0);
        }
        __syncthreads();

        uint32_t tb  = sb + 1024 + (ch & 1) * G1_SLOT;
        uint32_t tAh = tb, tAl = tb + 16384, tBh = tb + 32768, tBl = tb + 49152;

#pragma unroll
        for (int kk = 0; kk < 64; kk += 16) {
            uint32_t ah[8], al[8], b[16];
            LDSM_X4(ah[0], ah[1], ah[2], ah[3],
                    tAh + swz((uint32_t)((wm * 32 + a_r) * 128 + (kk + a_c) * 2)));
            LDSM_X4(ah[4], ah[5], ah[6], ah[7],
                    tAh + swz((uint32_t)((wm * 32 + 16 + a_r) * 128 + (kk + a_c) * 2)));
            LDSM_X4(al[0], al[1], al[2], al[3],
                    tAl + swz((uint32_t)((wm * 32 + a_r) * 128 + (kk + a_c) * 2)));
            LDSM_X4(al[4], al[5], al[6], al[7],
                    tAl + swz((uint32_t)((wm * 32 + 16 + a_r) * 128 + (kk + a_c) * 2)));
#pragma unroll
            for (int q = 0; q < 4; q++)
                LDSM_X4(b[4 * q], b[4 * q + 1], b[4 * q + 2], b[4 * q + 3],
                        tBh + swz((uint32_t)((wn * 64 + q * 16 + b_r) * 128 + (kk + b_c) * 2)));
#pragma unroll
            for (int mt = 0; mt < 2; mt++)
#pragma unroll
                for (int nt = 0; nt < 8; nt++)
                    mma_bf16(c[mt][nt], (mt ? ah + 4 : ah), b + 2 * nt);
#pragma unroll
            for (int mt = 0; mt < 2; mt++)
#pragma unroll
                for (int nt = 0; nt < 8; nt++)
                    mma_bf16(c[mt][nt], (mt ? al + 4 : al), b + 2 * nt);
#pragma unroll
            for (int q = 0; q < 4; q++)
                LDSM_X4(b[4 * q], b[4 * q + 1], b[4 * q + 2], b[4 * q + 3],
                        tBl + swz((uint32_t)((wn * 64 + q * 16 + b_r) * 128 + (kk + b_c) * 2)));
#pragma unroll
            for (int mt = 0; mt < 2; mt++)
#pragma unroll
                for (int nt = 0; nt < 8; nt++)
                    mma_bf16(c[mt][nt], (mt ? ah + 4 : ah), b + 2 * nt);
        }
        __syncthreads();
    }

    // ---- Epilogue: stage bf16 hi/lo in padded SMEM, then coalesced 16B stores
    char* Sh = smem + 1024;                    // [128][pitch 136 bf16] = 34 KB
    char* Sl = smem + 1024 + 34816;
#pragma unroll
    for (int mt = 0; mt < 2; mt++)
#pragma unroll
        for (int nt = 0; nt < 8; nt++)
#pragma unroll
            for (int h = 0; h < 2; h++) {
                int m = wm * 32 + mt * 16 + (lane >> 2) + h * 8;
                int n = wn * 64 + nt * 8 + (lane & 3) * 2;
                float f0 = c[mt][nt][2 * h], f1 = c[mt][nt][2 * h + 1];
                __nv_bfloat16 h0 = __float2bfloat16(f0);
                __nv_bfloat16 h1 = __float2bfloat16(f1);
                *reinterpret_cast<uint32_t*>(Sh + m * 272 + n * 2) = pack2bf(f0, f1);
                *reinterpret_cast<uint32_t*>(Sl + m * 272 + n * 2) =
                    pack2bf(f0 - __bfloat162float(h0), f1 - __bfloat162float(h1));
            }
    __syncthreads();
#pragma unroll
    for (int idx = tid; idx < 2048; idx += 256) {
        int row = idx >> 4, u = idx & 15;
        size_t ob = (size_t)(m0 + row) * (KOUT * D2) + (size_t)kb * D2 + n0 + u * 8;
        *reinterpret_cast<uint4*>(&g_th[ob]) =
            *reinterpret_cast<const uint4*>(Sh + row * 272 + u * 16);
        *reinterpret_cast<uint4*>(&g_tl[ob]) =
            *reinterpret_cast<const uint4*>(Sl + row * 272 + u * 16);
    }
}

// ---------------------------------------------------------------------------
// GEMM2: out[bi, j, k'] = sum_q X2[b,j,q] * tmp[bi,k',q] + bias[k']
//   grid (2, 2048), block 256.  Block tile 128(j) x 64(k'), K=512 in 8 chunks.
// SMEM: slot s at 1024 + s*48K:  Ah(16K) Al(16K) Bh(8K) Bl(8K).
// ---------------------------------------------------------------------------
#define G2_SLOT 49152
#define G2_SMEM (1024 + 2 * G2_SLOT)

__global__ __launch_bounds__(256) void gemm2_mma(
    const float* __restrict__ bias, float* __restrict__ out)
{
    extern __shared__ char smem[];
    uint32_t sb = smem_u32(smem);
    const int tid = threadIdx.x, wid = tid >> 5, lane = tid & 31;
    const int j0 = blockIdx.x * 128;
    const int bi = blockIdx.y;
    const int b  = bi >> 8;
    const int wm = wid & 3, wn = wid >> 2;       // warp tile 32(j) x 32(k')

    const __nv_bfloat16* Ah = g_x2h + ((size_t)b * L_SEQ + j0) * D2;
    const __nv_bfloat16* Al = g_x2l + ((size_t)b * L_SEQ + j0) * D2;
    const __nv_bfloat16* Bh = g_th + (size_t)bi * KOUT * D2;
    const __nv_bfloat16* Bl = g_tl + (size_t)bi * KOUT * D2;

    float c[2][4][4];
#pragma unroll
    for (int i = 0; i < 2; i++)
#pragma unroll
        for (int j = 0; j < 4; j++)
#pragma unroll
            for (int e = 0; e < 4; e++) c[i][j][e] = 0.0f;

    const int a_r = lane & 15, a_c = (lane >> 4) * 8;
    const int b_r = ((lane >> 4) & 1) * 8 + (lane & 7), b_c = ((lane >> 3) & 1) * 8;

    {
        uint32_t tb = sb + 1024;
        tile_cp<128>(Ah, tb, tid);
        tile_cp<128>(Al, tb + 16384, tid);
        tile_cp<64>(Bh, tb + 32768, tid);
        tile_cp<64>(Bl, tb + 40960, tid);
        CP_COMMIT();
    }

#pragma unroll 1
    for (int ch = 0; ch < 8; ch++) {
        if (ch < 7) {
            int q0 = (ch + 1) * 64;
            uint32_t tb = sb + 1024 + ((ch + 1) & 1) * G2_SLOT;
            tile_cp<128>(Ah + q0, tb, tid);
            tile_cp<128>(Al + q0, tb + 16384, tid);
            tile_cp<64>(Bh + q0, tb + 32768, tid);
            tile_cp<64>(Bl + q0, tb + 40960, tid);
            CP_COMMIT();
            CP_WAIT(1);
        } else {
            CP_WAIT(0);
        }
        __syncthreads();

        uint32_t tb  = sb + 1024 + (ch & 1) * G2_SLOT;
        uint32_t tAh = tb, tAl = tb + 16384, tBh = tb + 32768, tBl = tb + 40960;

#pragma unroll
        for (int kk = 0; kk < 64; kk += 16) {
            uint32_t ah[8], al[8], bg[8];
            LDSM_X4(ah[0], ah[1], ah[2], ah[3],
                    tAh + swz((uint32_t)((wm * 32 + a_r) * 128 + (kk + a_c) * 2)));
            LDSM_X4(ah[4], ah[5], ah[6], ah[7],
                    tAh + swz((uint32_t)((wm * 32 + 16 + a_r) * 128 + (kk + a_c) * 2)));
            LDSM_X4(al[0], al[1], al[2], al[3],
                    tAl + swz((uint32_t)((wm * 32 + a_r) * 128 + (kk + a_c) * 2)));
            LDSM_X4(al[4], al[5], al[6], al[7],
                    tAl + swz((uint32_t)((wm * 32 + 16 + a_r) * 128 + (kk + a_c) * 2)));
#pragma unroll
            for (int q = 0; q < 2; q++)
                LDSM_X4(bg[4 * q], bg[4 * q + 1], bg[4 * q + 2], bg[4 * q + 3],
                        tBh + swz((uint32_t)((wn * 32 + q * 16 + b_r) * 128 + (kk + b_c) * 2)));
#pragma unroll
            for (int mt = 0; mt < 2; mt++)
#pragma unroll
                for (int nt = 0; nt < 4; nt++)
                    mma_bf16(c[mt][nt], (mt ? ah + 4 : ah), bg + 2 * nt);
#pragma unroll
            for (int mt = 0; mt < 2; mt++)
#pragma unroll
                for (int nt = 0; nt < 4; nt++)
                    mma_bf16(c[mt][nt], (mt ? al + 4 : al), bg + 2 * nt);
#pragma unroll
            for (int q = 0; q < 2; q++)
                LDSM_X4(bg[4 * q], bg[4 * q + 1], bg[4 * q + 2], bg[4 * q + 3],
                        tBl + swz((uint32_t)((wn * 32 + q * 16 + b_r) * 128 + (kk + b_c) * 2)));
#pragma unroll
            for (int mt = 0; mt < 2; mt++)
#pragma unroll
                for (int nt = 0; nt < 4; nt++)
                    mma_bf16(c[mt][nt], (mt ? ah + 4 : ah), bg + 2 * nt);
        }
        __syncthreads();
    }

    // ---- Epilogue: direct f32 stores + bias
#pragma unroll
    for (int mt = 0; mt < 2; mt++)
#pragma unroll
        for (int nt = 0; nt < 4; nt++) {
            int n = wn * 32 + nt * 8 + (lane & 3) * 2;
            float2 bv = *reinterpret_cast<const float2*>(&bias[n]);
#pragma unroll
            for (int h = 0; h < 2; h++) {
                int m = wm * 32 + mt * 16 + (lane >> 2) + h * 8;
                size_t ob = ((size_t)bi * L_SEQ + j0 + m) * KOUT + n;
                float2 v;
                v.x = c[mt][nt][2 * h]     + bv.x;
                v.y = c[mt][nt][2 * h + 1] + bv.y;
                *reinterpret_cast<float2*>(&out[ob]) = v;
            }
        }
}

// ---------------------------------------------------------------------------
// Launch
// ---------------------------------------------------------------------------
extern "C" void kernel_launch(void* const* d_in, const int* in_sizes, int n_in,
                              void* d_out, int out_size)
{
    const float* x1   = (const float*)d_in[0];   // [8,256,512]
    const float* x2   = (const float*)d_in[1];   // [8,256,512]
    const float* w    = (const float*)d_in[2];   // [64,512,512]
    const float* bias = (const float*)d_in[3];   // [64]
    float* out = (float*)d_out;                  // [8,256,256,64]

    __nv_bfloat16 *a1h, *a1l, *x2h, *x2l;
    cudaGetSymbolAddress((void**)&a1h, g_a1h);
    cudaGetSymbolAddress((void**)&a1l, g_a1l);
    cudaGetSymbolAddress((void**)&x2h, g_x2h);
    cudaGetSymbolAddress((void**)&x2l, g_x2l);

    cudaFuncSetAttribute(gemm1_mma, cudaFuncAttributeMaxDynamicSharedMemorySize, G1_SMEM);
    cudaFuncSetAttribute(gemm2_mma, cudaFuncAttributeMaxDynamicSharedMemorySize, G2_SMEM);

    int n4 = M1 * D1 / 4;
    cvt_split_kernel<<<(n4 + 255) / 256, 256>>>(x1, a1h, a1l, n4);
    cvt_split_kernel<<<(n4 + 255) / 256, 256>>>(x2, x2h, x2l, n4);
    cvt_w_kernel<<<dim3(16, 16, 64), dim3(32, 8)>>>(w);

    gemm1_mma<<<dim3(16, 4, 64), 256, G1_SMEM>>>();
    gemm2_mma<<<dim3(2, 2048), 256, G2_SMEM>>>(bias, out);
}

// round 7
// speedup vs baseline: 2.9951x; 1.0102x over previous
#include <cuda_runtime.h>
#include <cuda_bf16.h>
#include <cstdint>

// ---------------------------------------------------------------------------
// Problem dims
// ---------------------------------------------------------------------------
#define B_BATCH 8
#define L_SEQ   256
#define D1      512
#define D2      512
#define KOUT    64
#define M1      (B_BATCH * L_SEQ)   // 2048 rows (b,i)

// ---------------------------------------------------------------------------
// Helpers (sm_80-era ISA only — harness PTX target is sm_103 without 'a')
// ---------------------------------------------------------------------------
__device__ __forceinline__ uint32_t smem_u32(const void* p) {
    uint32_t a;
    asm("{ .reg .u64 t; cvta.to.shared.u64 t, %1; cvt.u32.u64 %0, t; }"
        : "=r"(a) : "l"(p));
    return a;
}

// SW64 swizzle for 64-byte rows (8-row atom, conflict-free ldmatrix)
__device__ __forceinline__ uint32_t swz64(uint32_t off) {
    return off ^ ((off >> 3) & 0x30);
}

#define LDSM_X4(r0, r1, r2, r3, addr) \
    asm volatile("ldmatrix.sync.aligned.m8n8.x4.shared.b16 {%0,%1,%2,%3}, [%4];" \
        : "=r"(r0), "=r"(r1), "=r"(r2), "=r"(r3) : "r"(addr))

#define CP_ASYNC16(smem_addr, gptr) \
    asm volatile("cp.async.cg.shared.global [%0], [%1], 16;" \
        :: "r"(smem_addr), "l"(gptr))

#define CP_COMMIT()  asm volatile("cp.async.commit_group;" ::: "memory")
#define CP_WAIT(N)   asm volatile("cp.async.wait_group %0;" :: "n"(N) : "memory")

__device__ __forceinline__ void mma_bf16(float* c, const uint32_t* a, const uint32_t* b) {
    asm volatile(
        "mma.sync.aligned.m16n8k16.row.col.f32.bf16.bf16.f32 "
        "{%0,%1,%2,%3}, {%4,%5,%6,%7}, {%8,%9}, {%0,%1,%2,%3};"
        : "+f"(c[0]), "+f"(c[1]), "+f"(c[2]), "+f"(c[3])
        : "r"(a[0]), "r"(a[1]), "r"(a[2]), "r"(a[3]), "r"(b[0]), "r"(b[1]));
}

__device__ __forceinline__ uint32_t pack2bf(float a, float b) {
    __nv_bfloat162 t = __floats2bfloat162_rn(a, b);
    return *reinterpret_cast<uint32_t*>(&t);
}

// ---------------------------------------------------------------------------
// Scratch
// ---------------------------------------------------------------------------
__device__ __align__(256) __nv_bfloat16 g_a1h[(size_t)M1 * D1];
__device__ __align__(256) __nv_bfloat16 g_a1l[(size_t)M1 * D1];
__device__ __align__(256) __nv_bfloat16 g_x2h[(size_t)M1 * D2];
__device__ __align__(256) __nv_bfloat16 g_x2l[(size_t)M1 * D2];
__device__ __align__(256) __nv_bfloat16 g_wth[(size_t)KOUT * D2 * D1];  // W^T hi [k][q][p]
__device__ __align__(256) __nv_bfloat16 g_wtl[(size_t)KOUT * D2 * D1];  // W^T lo
__device__ __align__(256) __nv_bfloat16 g_th[(size_t)M1 * KOUT * D2];   // tmp hi [m][k][q]
__device__ __align__(256) __nv_bfloat16 g_tl[(size_t)M1 * KOUT * D2];   // tmp lo

// ---------------------------------------------------------------------------
// Conversion kernels
// ---------------------------------------------------------------------------
__global__ __launch_bounds__(256) void cvt_split_kernel(
    const float* __restrict__ in, __nv_bfloat16* __restrict__ hi,
    __nv_bfloat16* __restrict__ lo, int n4)
{
    int i = blockIdx.x * 256 + threadIdx.x;
    if (i >= n4) return;
    float4 v = reinterpret_cast<const float4*>(in)[i];
    __nv_bfloat16 h0 = __float2bfloat16(v.x);
    __nv_bfloat16 h1 = __float2bfloat16(v.y);
    __nv_bfloat16 h2 = __float2bfloat16(v.z);
    __nv_bfloat16 h3 = __float2bfloat16(v.w);
    reinterpret_cast<__nv_bfloat162*>(hi)[2 * i]     = __halves2bfloat162(h0, h1);
    reinterpret_cast<__nv_bfloat162*>(hi)[2 * i + 1] = __halves2bfloat162(h2, h3);
    reinterpret_cast<__nv_bfloat162*>(lo)[2 * i] = __halves2bfloat162(
        __float2bfloat16(v.x - __bfloat162float(h0)),
        __float2bfloat16(v.y - __bfloat162float(h1)));
    reinterpret_cast<__nv_bfloat162*>(lo)[2 * i + 1] = __halves2bfloat162(
        __float2bfloat16(v.z - __bfloat162float(h2)),
        __float2bfloat16(v.w - __bfloat162float(h3)));
}

// W[k][p][q] -> Wt[k][q][p], bf16 hi/lo.  grid (16,16,64), block (32,8)
__global__ void cvt_w_kernel(const float* __restrict__ W)
{
    __shared__ float t[32][33];
    int k  = blockIdx.z;
    int q0 = blockIdx.x * 32;
    int p0 = blockIdx.y * 32;
    const float* Wk = W + (size_t)k * D1 * D2;
    int tx = threadIdx.x, ty = threadIdx.y;
#pragma unroll
    for (int i = 0; i < 4; i++)
        t[ty + 8 * i][tx] = Wk[(size_t)(p0 + ty + 8 * i) * D2 + q0 + tx];
    __syncthreads();
#pragma unroll
    for (int i = 0; i < 4; i++) {
        float v = t[tx][ty + 8 * i];
        size_t o = (size_t)k * D2 * D1 + (size_t)(q0 + ty + 8 * i) * D1 + p0 + tx;
        __nv_bfloat16 h = __float2bfloat16(v);
        g_wth[o] = h;
        g_wtl[o] = __float2bfloat16(v - __bfloat162float(h));
    }
}

// ---------------------------------------------------------------------------
// Async tile copy: ROWS rows x 32 bf16 (64B rows), gmem pitch 512 elems,
// into SW64-swizzled SMEM.
// ---------------------------------------------------------------------------
template <int ROWS>
__device__ __forceinline__ void tile_cp32(
    const __nv_bfloat16* __restrict__ g, uint32_t s, int tid)
{
#pragma unroll
    for (int idx = tid; idx < ROWS * 4; idx += 256) {
        int row = idx >> 2, u = idx & 3;
        CP_ASYNC16(s + swz64((uint32_t)(row * 64 + u * 16)),
                   g + (size_t)row * 512 + u * 8);
    }
}

// ---------------------------------------------------------------------------
// GEMM1: tmp[m, kb, q] = sum_p X1[m,p] * W[kb,p,q]   (3-pass bf16 hi/lo)
//   grid (16, 4, 64), block 256 (8 warps), 2 CTAs/SM.
//   Block tile 128(m) x 128(q), K=512 in 16 chunks of 32, double-buffered.
// SMEM slot (32 KB): Ah(8K) Al(8K) Bh(8K) Bl(8K), 64B rows, SW64.
// Epilogue stages hi/lo bf16 via padded SMEM.
// ---------------------------------------------------------------------------
#define G1_SLOT 32768
#define G1_SMEM (1024 + 2 * 34816)   // 70656: epilogue staging is the max user

__global__ __launch_bounds__(256, 2) void gemm1_mma(void)
{
    extern __shared__ char smem[];
    uint32_t sb = smem_u32(smem);
    const int tid = threadIdx.x, wid = tid >> 5, lane = tid & 31;
    const int m0 = blockIdx.x * 128, n0 = blockIdx.y * 128, kb = blockIdx.z;
    const int wm = wid & 3, wn = wid >> 2;       // warp tile 32(m) x 64(n)

    const __nv_bfloat16* Ah = g_a1h + (size_t)m0 * D1;
    const __nv_bfloat16* Al = g_a1l + (size_t)m0 * D1;
    const __nv_bfloat16* Bh = g_wth + ((size_t)kb * D2 + n0) * D1;
    const __nv_bfloat16* Bl = g_wtl + ((size_t)kb * D2 + n0) * D1;

    float c[2][8][4];
#pragma unroll
    for (int i = 0; i < 2; i++)
#pragma unroll
        for (int j = 0; j < 8; j++)
#pragma unroll
            for (int e = 0; e < 4; e++) c[i][j][e] = 0.0f;

    const int a_r = lane & 15, a_c = (lane >> 4) * 8;
    const int b_r = ((lane >> 4) & 1) * 8 + (lane & 7), b_c = ((lane >> 3) & 1) * 8;

    // prologue: chunk 0 -> slot 0
    {
        uint32_t tb = sb + 1024;
        tile_cp32<128>(Ah, tb, tid);
        tile_cp32<128>(Al, tb + 8192, tid);
        tile_cp32<128>(Bh, tb + 16384, tid);
        tile_cp32<128>(Bl, tb + 24576, tid);
        CP_COMMIT();
    }

#pragma unroll 1
    for (int ch = 0; ch < 16; ch++) {
        if (ch < 15) {
            int p0 = (ch + 1) * 32;
            uint32_t tb = sb + 1024 + ((ch + 1) & 1) * G1_SLOT;
            tile_cp32<128>(Ah + p0, tb, tid);
            tile_cp32<128>(Al + p0, tb + 8192, tid);
            tile_cp32<128>(Bh + p0, tb + 16384, tid);
            tile_cp32<128>(Bl + p0, tb + 24576, tid);
            CP_COMMIT();
            CP_WAIT(1);
        } else {
            CP_WAIT(0);
        }
        __syncthreads();

        uint32_t tb  = sb + 1024 + (ch & 1) * G1_SLOT;
        uint32_t tAh = tb, tAl = tb + 8192, tBh = tb + 16384, tBl = tb + 24576;

#pragma unroll
        for (int kk = 0; kk < 32; kk += 16) {
            uint32_t ah[8], al[8], b[16];
            LDSM_X4(ah[0], ah[1], ah[2], ah[3],
                    tAh + swz64((uint32_t)((wm * 32 + a_r) * 64 + (kk + a_c) * 2)));
            LDSM_X4(ah[4], ah[5], ah[6], ah[7],
                    tAh + swz64((uint32_t)((wm * 32 + 16 + a_r) * 64 + (kk + a_c) * 2)));
            LDSM_X4(al[0], al[1], al[2], al[3],
                    tAl + swz64((uint32_t)((wm * 32 + a_r) * 64 + (kk + a_c) * 2)));
            LDSM_X4(al[4], al[5], al[6], al[7],
                    tAl + swz64((uint32_t)((wm * 32 + 16 + a_r) * 64 + (kk + a_c) * 2)));
#pragma unroll
            for (int q = 0; q < 4; q++)
                LDSM_X4(b[4 * q], b[4 * q + 1], b[4 * q + 2], b[4 * q + 3],
                        tBh + swz64((uint32_t)((wn * 64 + q * 16 + b_r) * 64 + (kk + b_c) * 2)));
#pragma unroll
            for (int mt = 0; mt < 2; mt++)
#pragma unroll
                for (int nt = 0; nt < 8; nt++)
                    mma_bf16(c[mt][nt], (mt ? ah + 4 : ah), b + 2 * nt);
#pragma unroll
            for (int mt = 0; mt < 2; mt++)
#pragma unroll
                for (int nt = 0; nt < 8; nt++)
                    mma_bf16(c[mt][nt], (mt ? al + 4 : al), b + 2 * nt);
#pragma unroll
            for (int q = 0; q < 4; q++)
                LDSM_X4(b[4 * q], b[4 * q + 1], b[4 * q + 2], b[4 * q + 3],
                        tBl + swz64((uint32_t)((wn * 64 + q * 16 + b_r) * 64 + (kk + b_c) * 2)));
#pragma unroll
            for (int mt = 0; mt < 2; mt++)
#pragma unroll
                for (int nt = 0; nt < 8; nt++)
                    mma_bf16(c[mt][nt], (mt ? ah + 4 : ah), b + 2 * nt);
        }
        __syncthreads();
    }

    // ---- Epilogue: stage bf16 hi/lo in padded SMEM, then coalesced 16B stores
    char* Sh = smem + 1024;                    // [128][pitch 136 bf16] = 34 KB
    char* Sl = smem + 1024 + 34816;
#pragma unroll
    for (int mt = 0; mt < 2; mt++)
#pragma unroll
        for (int nt = 0; nt < 8; nt++)
#pragma unroll
            for (int h = 0; h < 2; h++) {
                int m = wm * 32 + mt * 16 + (lane >> 2) + h * 8;
                int n = wn * 64 + nt * 8 + (lane & 3) * 2;
                float f0 = c[mt][nt][2 * h], f1 = c[mt][nt][2 * h + 1];
                __nv_bfloat16 h0 = __float2bfloat16(f0);
                __nv_bfloat16 h1 = __float2bfloat16(f1);
                *reinterpret_cast<uint32_t*>(Sh + m * 272 + n * 2) = pack2bf(f0, f1);
                *reinterpret_cast<uint32_t*>(Sl + m * 272 + n * 2) =
                    pack2bf(f0 - __bfloat162float(h0), f1 - __bfloat162float(h1));
            }
    __syncthreads();
#pragma unroll
    for (int idx = tid; idx < 2048; idx += 256) {
        int row = idx >> 4, u = idx & 15;
        size_t ob = (size_t)(m0 + row) * (KOUT * D2) + (size_t)kb * D2 + n0 + u * 8;
        *reinterpret_cast<uint4*>(&g_th[ob]) =
            *reinterpret_cast<const uint4*>(Sh + row * 272 + u * 16);
        *reinterpret_cast<uint4*>(&g_tl[ob]) =
            *reinterpret_cast<const uint4*>(Sl + row * 272 + u * 16);
    }
}

// ---------------------------------------------------------------------------
// GEMM2: out[bi, j, k'] = sum_q X2[b,j,q] * tmp[bi,k',q] + bias[k']
//   grid (2048), block 256 (8 warps), 2 CTAs/SM.
//   Block tile 256(j) x 64(k'), one block per bi. K=512 in 16 chunks of 32.
// SMEM slot (40 KB): Ah(16K) Al(16K) Bh(4K) Bl(4K), 64B rows, SW64.
//   Warp tile 64(j) x 32(k'); A regs reloaded (ah then al) to stay <=128 regs.
// ---------------------------------------------------------------------------
#define G2_SLOT 40960
#define G2_SMEM (1024 + 2 * G2_SLOT)

__global__ __launch_bounds__(256, 2) void gemm2_mma(
    const float* __restrict__ bias, float* __restrict__ out)
{
    extern __shared__ char smem[];
    uint32_t sb = smem_u32(smem);
    const int tid = threadIdx.x, wid = tid >> 5, lane = tid & 31;
    const int bi = blockIdx.x;
    const int b  = bi >> 8;
    const int wm = wid & 3, wn = wid >> 2;       // warp tile 64(j) x 32(k')

    const __nv_bfloat16* Ah = g_x2h + (size_t)b * L_SEQ * D2;
    const __nv_bfloat16* Al = g_x2l + (size_t)b * L_SEQ * D2;
    const __nv_bfloat16* Bh = g_th + (size_t)bi * KOUT * D2;
    const __nv_bfloat16* Bl = g_tl + (size_t)bi * KOUT * D2;

    float c[4][4][4];
#pragma unroll
    for (int i = 0; i < 4; i++)
#pragma unroll
        for (int j = 0; j < 4; j++)
#pragma unroll
            for (int e = 0; e < 4; e++) c[i][j][e] = 0.0f;

    const int a_r = lane & 15, a_c = (lane >> 4) * 8;
    const int b_r = ((lane >> 4) & 1) * 8 + (lane & 7), b_c = ((lane >> 3) & 1) * 8;

    {
        uint32_t tb = sb + 1024;
        tile_cp32<256>(Ah, tb, tid);
        tile_cp32<256>(Al, tb + 16384, tid);
        tile_cp32<64>(Bh, tb + 32768, tid);
        tile_cp32<64>(Bl, tb + 36864, tid);
        CP_COMMIT();
    }

#pragma unroll 1
    for (int ch = 0; ch < 16; ch++) {
        if (ch < 15) {
            int q0 = (ch + 1) * 32;
            uint32_t tb = sb + 1024 + ((ch + 1) & 1) * G2_SLOT;
            tile_cp32<256>(Ah + q0, tb, tid);
            tile_cp32<256>(Al + q0, tb + 16384, tid);
            tile_cp32<64>(Bh + q0, tb + 32768, tid);
            tile_cp32<64>(Bl + q0, tb + 36864, tid);
            CP_COMMIT();
            CP_WAIT(1);
        } else {
            CP_WAIT(0);
        }
        __syncthreads();

        uint32_t tb  = sb + 1024 + (ch & 1) * G2_SLOT;
        uint32_t tAh = tb, tAl = tb + 16384, tBh = tb + 32768, tBl = tb + 36864;

#pragma unroll
        for (int kk = 0; kk < 32; kk += 16) {
            uint32_t a[16], bh[8], bl[8];
            // A hi: 4 m-subtiles of 16 rows
#pragma unroll
            for (int mt = 0; mt < 4; mt++)
                LDSM_X4(a[4 * mt], a[4 * mt + 1], a[4 * mt + 2], a[4 * mt + 3],
                        tAh + swz64((uint32_t)((wm * 64 + mt * 16 + a_r) * 64 + (kk + a_c) * 2)));
#pragma unroll
            for (int q = 0; q < 2; q++)
                LDSM_X4(bh[4 * q], bh[4 * q + 1], bh[4 * q + 2], bh[4 * q + 3],
                        tBh + swz64((uint32_t)((wn * 32 + q * 16 + b_r) * 64 + (kk + b_c) * 2)));
#pragma unroll
            for (int q = 0; q < 2; q++)
                LDSM_X4(bl[4 * q], bl[4 * q + 1], bl[4 * q + 2], bl[4 * q + 3],
                        tBl + swz64((uint32_t)((wn * 32 + q * 16 + b_r) * 64 + (kk + b_c) * 2)));
            // pass 1: Ah * Bh
#pragma unroll
            for (int mt = 0; mt < 4; mt++)
#pragma unroll
                for (int nt = 0; nt < 4; nt++)
                    mma_bf16(c[mt][nt], a + 4 * mt, bh + 2 * nt);
            // pass 3: Ah * Bl
#pragma unroll
            for (int mt = 0; mt < 4; mt++)
#pragma unroll
                for (int nt = 0; nt < 4; nt++)
                    mma_bf16(c[mt][nt], a + 4 * mt, bl + 2 * nt);
            // A lo (reload over a)
#pragma unroll
            for (int mt = 0; mt < 4; mt++)
                LDSM_X4(a[4 * mt], a[4 * mt + 1], a[4 * mt + 2], a[4 * mt + 3],
                        tAl + swz64((uint32_t)((wm * 64 + mt * 16 + a_r) * 64 + (kk + a_c) * 2)));
            // pass 2: Al * Bh
#pragma unroll
            for (int mt = 0; mt < 4; mt++)
#pragma unroll
                for (int nt = 0; nt < 4; nt++)
                    mma_bf16(c[mt][nt], a + 4 * mt, bh + 2 * nt);
        }
        __syncthreads();
    }

    // ---- Epilogue: direct f32 stores + bias
#pragma unroll
    for (int mt = 0; mt < 4; mt++)
#pragma unroll
        for (int nt = 0; nt < 4; nt++) {
            int n = wn * 32 + nt * 8 + (lane & 3) * 2;
            float2 bv = *reinterpret_cast<const float2*>(&bias[n]);
#pragma unroll
            for (int h = 0; h < 2; h++) {
                int m = wm * 64 + mt * 16 + (lane >> 2) + h * 8;
                size_t ob = ((size_t)bi * L_SEQ + m) * KOUT + n;
                float2 v;
                v.x = c[mt][nt][2 * h]     + bv.x;
                v.y = c[mt][nt][2 * h + 1] + bv.y;
                *reinterpret_cast<float2*>(&out[ob]) = v;
            }
        }
}

// ---------------------------------------------------------------------------
// Launch
// ---------------------------------------------------------------------------
extern "C" void kernel_launch(void* const* d_in, const int* in_sizes, int n_in,
                              void* d_out, int out_size)
{
    const float* x1   = (const float*)d_in[0];   // [8,256,512]
    const float* x2   = (const float*)d_in[1];   // [8,256,512]
    const float* w    = (const float*)d_in[2];   // [64,512,512]
    const float* bias = (const float*)d_in[3];   // [64]
    float* out = (float*)d_out;                  // [8,256,256,64]

    __nv_bfloat16 *a1h, *a1l, *x2h, *x2l;
    cudaGetSymbolAddress((void**)&a1h, g_a1h);
    cudaGetSymbolAddress((void**)&a1l, g_a1l);
    cudaGetSymbolAddress((void**)&x2h, g_x2h);
    cudaGetSymbolAddress((void**)&x2l, g_x2l);

    cudaFuncSetAttribute(gemm1_mma, cudaFuncAttributeMaxDynamicSharedMemorySize, G1_SMEM);
    cudaFuncSetAttribute(gemm2_mma, cudaFuncAttributeMaxDynamicSharedMemorySize, G2_SMEM);

    int n4 = M1 * D1 / 4;
    cvt_split_kernel<<<(n4 + 255) / 256, 256>>>(x1, a1h, a1l, n4);
    cvt_split_kernel<<<(n4 + 255) / 256, 256>>>(x2, x2h, x2l, n4);
    cvt_w_kernel<<<dim3(16, 16, 64), dim3(32, 8)>>>(w);

    gemm1_mma<<<dim3(16, 4, 64), 256, G1_SMEM>>>();
    gemm2_mma<<<2048, 256, G2_SMEM>>>(bias, out);
}

// round 8
// speedup vs baseline: 4.3873x; 1.4649x over previous
#include <cuda_runtime.h>
#include <cuda_fp16.h>
#include <cstdint>

// ---------------------------------------------------------------------------
// Problem dims
// ---------------------------------------------------------------------------
#define B_BATCH 8
#define L_SEQ   256
#define D1      512
#define D2      512
#define KOUT    64
#define M1      (B_BATCH * L_SEQ)   // 2048 rows (b,i)

// ---------------------------------------------------------------------------
// Helpers (sm_80-era ISA only — harness PTX target is sm_103 without 'a')
// ---------------------------------------------------------------------------
__device__ __forceinline__ uint32_t smem_u32(const void* p) {
    uint32_t a;
    asm("{ .reg .u64 t; cvta.to.shared.u64 t, %1; cvt.u32.u64 %0, t; }"
        : "=r"(a) : "l"(p));
    return a;
}

__device__ __forceinline__ uint32_t swz128(uint32_t off) {  // 128B-row swizzle
    return off ^ ((off >> 3) & 0x70);
}
__device__ __forceinline__ uint32_t swz64(uint32_t off) {   // 64B-row swizzle
    return off ^ ((off >> 3) & 0x30);
}

#define LDSM_X4(r0, r1, r2, r3, addr) \
    asm volatile("ldmatrix.sync.aligned.m8n8.x4.shared.b16 {%0,%1,%2,%3}, [%4];" \
        : "=r"(r0), "=r"(r1), "=r"(r2), "=r"(r3) : "r"(addr))

#define CP_ASYNC16(smem_addr, gptr) \
    asm volatile("cp.async.cg.shared.global [%0], [%1], 16;" \
        :: "r"(smem_addr), "l"(gptr))

#define CP_COMMIT()  asm volatile("cp.async.commit_group;" ::: "memory")
#define CP_WAIT(N)   asm volatile("cp.async.wait_group %0;" :: "n"(N) : "memory")

__device__ __forceinline__ void mma_fp16(float* c, const uint32_t* a, const uint32_t* b) {
    asm volatile(
        "mma.sync.aligned.m16n8k16.row.col.f32.f16.f16.f32 "
        "{%0,%1,%2,%3}, {%4,%5,%6,%7}, {%8,%9}, {%0,%1,%2,%3};"
        : "+f"(c[0]), "+f"(c[1]), "+f"(c[2]), "+f"(c[3])
        : "r"(a[0]), "r"(a[1]), "r"(a[2]), "r"(a[3]), "r"(b[0]), "r"(b[1]));
}

__device__ __forceinline__ uint32_t pack2h(float a, float b) {
    __half2 t = __floats2half2_rn(a, b);
    return *reinterpret_cast<uint32_t*>(&t);
}

// ---------------------------------------------------------------------------
// Scratch
// ---------------------------------------------------------------------------
__device__ __align__(256) __half g_a1h[(size_t)M1 * D1];            // X1 hi
__device__ __align__(256) __half g_a1l[(size_t)M1 * D1];            // X1 lo
__device__ __align__(256) __half g_x2h[(size_t)M1 * D2];            // X2 hi
__device__ __align__(256) __half g_x2l[(size_t)M1 * D2];            // X2 lo
__device__ __align__(256) __half g_wt[(size_t)KOUT * D2 * D1];      // W^T fp16 [k][q][p]
__device__ __align__(256) __half g_t[(size_t)M1 * KOUT * D2];       // tmp fp16 [m][k][q]

// ---------------------------------------------------------------------------
// Conversion kernels
// ---------------------------------------------------------------------------
__global__ __launch_bounds__(256) void cvt_split_kernel(
    const float* __restrict__ in, __half* __restrict__ hi,
    __half* __restrict__ lo, int n4)
{
    int i = blockIdx.x * 256 + threadIdx.x;
    if (i >= n4) return;
    float4 v = reinterpret_cast<const float4*>(in)[i];
    __half h0 = __float2half_rn(v.x);
    __half h1 = __float2half_rn(v.y);
    __half h2 = __float2half_rn(v.z);
    __half h3 = __float2half_rn(v.w);
    reinterpret_cast<__half2*>(hi)[2 * i]     = __halves2half2(h0, h1);
    reinterpret_cast<__half2*>(hi)[2 * i + 1] = __halves2half2(h2, h3);
    reinterpret_cast<__half2*>(lo)[2 * i] = __halves2half2(
        __float2half_rn(v.x - __half2float(h0)),
        __float2half_rn(v.y - __half2float(h1)));
    reinterpret_cast<__half2*>(lo)[2 * i + 1] = __halves2half2(
        __float2half_rn(v.z - __half2float(h2)),
        __float2half_rn(v.w - __half2float(h3)));
}

// W[k][p][q] -> Wt[k][q][p] fp16.  grid (16,16,64), block (32,8)
__global__ void cvt_w_kernel(const float* __restrict__ W)
{
    __shared__ float t[32][33];
    int k  = blockIdx.z;
    int q0 = blockIdx.x * 32;
    int p0 = blockIdx.y * 32;
    const float* Wk = W + (size_t)k * D1 * D2;
    int tx = threadIdx.x, ty = threadIdx.y;
#pragma unroll
    for (int i = 0; i < 4; i++)
        t[ty + 8 * i][tx] = Wk[(size_t)(p0 + ty + 8 * i) * D2 + q0 + tx];
    __syncthreads();
#pragma unroll
    for (int i = 0; i < 4; i++) {
        size_t o = (size_t)k * D2 * D1 + (size_t)(q0 + ty + 8 * i) * D1 + p0 + tx;
        g_wt[o] = __float2half_rn(t[tx][ty + 8 * i]);
    }
}

// ---------------------------------------------------------------------------
// Tile copies: gmem pitch 512 halves -> swizzled SMEM
// ---------------------------------------------------------------------------
template <int ROWS>   // 128B rows (64 halves), SW128
__device__ __forceinline__ void tile_cp64(
    const __half* __restrict__ g, uint32_t s, int tid)
{
#pragma unroll
    for (int idx = tid; idx < ROWS * 8; idx += 256) {
        int row = idx >> 3, u = idx & 7;
        CP_ASYNC16(s + swz128((uint32_t)(row * 128 + u * 16)),
                   g + (size_t)row * 512 + u * 8);
    }
}

template <int ROWS>   // 64B rows (32 halves), SW64
__device__ __forceinline__ void tile_cp32(
    const __half* __restrict__ g, uint32_t s, int tid)
{
#pragma unroll
    for (int idx = tid; idx < ROWS * 4; idx += 256) {
        int row = idx >> 2, u = idx & 3;
        CP_ASYNC16(s + swz64((uint32_t)(row * 64 + u * 16)),
                   g + (size_t)row * 512 + u * 8);
    }
}

// ---------------------------------------------------------------------------
// GEMM1: tmp[m, kb, q] = sum_p X1[m,p] * W[kb,p,q]
//   2-pass fp16: x1h*Wh + x1l*Wh = x1 * fp16(W)
//   grid (16, 4, 64), block 256 (8 warps), 2 CTAs/SM.
//   Block tile 128(m) x 128(q), K=512 in 8 chunks of 64, double-buffered.
// SMEM slot (48 KB): Ah(16K) Al(16K) Bh(16K), 128B rows, SW128.
// Epilogue stages fp16 via padded SMEM.
// ---------------------------------------------------------------------------
#define G1_SLOT 49152
#define G1_SMEM (1024 + 2 * G1_SLOT)   // 99328 -> 2 CTAs/SM

__global__ __launch_bounds__(256, 2) void gemm1_mma(void)
{
    extern __shared__ char smem[];
    uint32_t sb = smem_u32(smem);
    const int tid = threadIdx.x, wid = tid >> 5, lane = tid & 31;
    const int m0 = blockIdx.x * 128, n0 = blockIdx.y * 128, kb = blockIdx.z;
    const int wm = wid & 3, wn = wid >> 2;       // warp tile 32(m) x 64(n)

    const __half* Ah = g_a1h + (size_t)m0 * D1;
    const __half* Al = g_a1l + (size_t)m0 * D1;
    const __half* Bh = g_wt + ((size_t)kb * D2 + n0) * D1;

    float c[2][8][4];
#pragma unroll
    for (int i = 0; i < 2; i++)
#pragma unroll
        for (int j = 0; j < 8; j++)
#pragma unroll
            for (int e = 0; e < 4; e++) c[i][j][e] = 0.0f;

    const int a_r = lane & 15, a_c = (lane >> 4) * 8;
    const int b_r = ((lane >> 4) & 1) * 8 + (lane & 7), b_c = ((lane >> 3) & 1) * 8;

    // prologue: chunk 0 -> slot 0
    {
        uint32_t tb = sb + 1024;
        tile_cp64<128>(Ah, tb, tid);
        tile_cp64<128>(Al, tb + 16384, tid);
        tile_cp64<128>(Bh, tb + 32768, tid);
        CP_COMMIT();
    }

#pragma unroll 1
    for (int ch = 0; ch < 8; ch++) {
        if (ch < 7) {
            int p0 = (ch + 1) * 64;
            uint32_t tb = sb + 1024 + ((ch + 1) & 1) * G1_SLOT;
            tile_cp64<128>(Ah + p0, tb, tid);
            tile_cp64<128>(Al + p0, tb + 16384, tid);
            tile_cp64<128>(Bh + p0, tb + 32768, tid);
            CP_COMMIT();
            CP_WAIT(1);
        } else {
            CP_WAIT(0);
        }
        __syncthreads();

        uint32_t tb  = sb + 1024 + (ch & 1) * G1_SLOT;
        uint32_t tAh = tb, tAl = tb + 16384, tBh = tb + 32768;

#pragma unroll
        for (int kk = 0; kk < 64; kk += 16) {
            uint32_t ah[8], al[8], b[16];
            LDSM_X4(ah[0], ah[1], ah[2], ah[3],
                    tAh + swz128((uint32_t)((wm * 32 + a_r) * 128 + (kk + a_c) * 2)));
            LDSM_X4(ah[4], ah[5], ah[6], ah[7],
                    tAh + swz128((uint32_t)((wm * 32 + 16 + a_r) * 128 + (kk + a_c) * 2)));
            LDSM_X4(al[0], al[1], al[2], al[3],
                    tAl + swz128((uint32_t)((wm * 32 + a_r) * 128 + (kk + a_c) * 2)));
            LDSM_X4(al[4], al[5], al[6], al[7],
                    tAl + swz128((uint32_t)((wm * 32 + 16 + a_r) * 128 + (kk + a_c) * 2)));
#pragma unroll
            for (int q = 0; q < 4; q++)
                LDSM_X4(b[4 * q], b[4 * q + 1], b[4 * q + 2], b[4 * q + 3],
                        tBh + swz128((uint32_t)((wn * 64 + q * 16 + b_r) * 128 + (kk + b_c) * 2)));
            // pass 1: x1h * Wh
#pragma unroll
            for (int mt = 0; mt < 2; mt++)
#pragma unroll
                for (int nt = 0; nt < 8; nt++)
                    mma_fp16(c[mt][nt], (mt ? ah + 4 : ah), b + 2 * nt);
            // pass 2: x1l * Wh
#pragma unroll
            for (int mt = 0; mt < 2; mt++)
#pragma unroll
                for (int nt = 0; nt < 8; nt++)
                    mma_fp16(c[mt][nt], (mt ? al + 4 : al), b + 2 * nt);
        }
        __syncthreads();
    }

    // ---- Epilogue: stage fp16 in padded SMEM, then coalesced 16B stores
    char* Sh = smem + 1024;                    // [128][pitch 136 half] = 34 KB
#pragma unroll
    for (int mt = 0; mt < 2; mt++)
#pragma unroll
        for (int nt = 0; nt < 8; nt++)
#pragma unroll
            for (int h = 0; h < 2; h++) {
                int m = wm * 32 + mt * 16 + (lane >> 2) + h * 8;
                int n = wn * 64 + nt * 8 + (lane & 3) * 2;
                *reinterpret_cast<uint32_t*>(Sh + m * 272 + n * 2) =
                    pack2h(c[mt][nt][2 * h], c[mt][nt][2 * h + 1]);
            }
    __syncthreads();
#pragma unroll
    for (int idx = tid; idx < 1024; idx += 256) {
        int row = idx >> 3, u = idx & 7;
        size_t ob = (size_t)(m0 + row) * (KOUT * D2) + (size_t)kb * D2 + n0 + u * 16;
        *reinterpret_cast<uint4*>(&g_t[ob]) =
            *reinterpret_cast<const uint4*>(Sh + row * 272 + u * 32);
        *reinterpret_cast<uint4*>(&g_t[ob + 8]) =
            *reinterpret_cast<const uint4*>(Sh + row * 272 + u * 32 + 16);
    }
}

// ---------------------------------------------------------------------------
// GEMM2: out[bi, j, k'] = sum_q X2[b,j,q] * tmp[bi,k',q] + bias[k']
//   2-pass fp16: x2h*tmph + x2l*tmph = x2 * fp16(tmp)
//   grid (2048), block 256 (8 warps), 2 CTAs/SM.
//   Block tile 256(j) x 64(k'), one block per bi. K=512 in 16 chunks of 32.
// SMEM slot (36 KB): Ah(16K) Al(16K) Bh(4K), 64B rows, SW64.
//   Warp tile 64(j) x 32(k'); A regs reloaded (ah then al) to stay <=128 regs.
// ---------------------------------------------------------------------------
#define G2_SLOT 36864
#define G2_SMEM (1024 + 2 * G2_SLOT)   // 74752 -> 2 CTAs/SM

__global__ __launch_bounds__(256, 2) void gemm2_mma(
    const float* __restrict__ bias, float* __restrict__ out)
{
    extern __shared__ char smem[];
    uint32_t sb = smem_u32(smem);
    const int tid = threadIdx.x, wid = tid >> 5, lane = tid & 31;
    const int bi = blockIdx.x;
    const int b  = bi >> 8;
    const int wm = wid & 3, wn = wid >> 2;       // warp tile 64(j) x 32(k')

    const __half* Ah = g_x2h + (size_t)b * L_SEQ * D2;
    const __half* Al = g_x2l + (size_t)b * L_SEQ * D2;
    const __half* Bh = g_t + (size_t)bi * KOUT * D2;

    float c[4][4][4];
#pragma unroll
    for (int i = 0; i < 4; i++)
#pragma unroll
        for (int j = 0; j < 4; j++)
#pragma unroll
            for (int e = 0; e < 4; e++) c[i][j][e] = 0.0f;

    const int a_r = lane & 15, a_c = (lane >> 4) * 8;
    const int b_r = ((lane >> 4) & 1) * 8 + (lane & 7), b_c = ((lane >> 3) & 1) * 8;

    {
        uint32_t tb = sb + 1024;
        tile_cp32<256>(Ah, tb, tid);
        tile_cp32<256>(Al, tb + 16384, tid);
        tile_cp32<64>(Bh, tb + 32768, tid);
        CP_COMMIT();
    }

#pragma unroll 1
    for (int ch = 0; ch < 16; ch++) {
        if (ch < 15) {
            int q0 = (ch + 1) * 32;
            uint32_t tb = sb + 1024 + ((ch + 1) & 1) * G2_SLOT;
            tile_cp32<256>(Ah + q0, tb, tid);
            tile_cp32<256>(Al + q0, tb + 16384, tid);
            tile_cp32<64>(Bh + q0, tb + 32768, tid);
            CP_COMMIT();
            CP_WAIT(1);
        } else {
            CP_WAIT(0);
        }
        __syncthreads();

        uint32_t tb  = sb + 1024 + (ch & 1) * G2_SLOT;
        uint32_t tAh = tb, tAl = tb + 16384, tBh = tb + 32768;

#pragma unroll
        for (int kk = 0; kk < 32; kk += 16) {
            uint32_t a[16], bh[8];
#pragma unroll
            for (int q = 0; q < 2; q++)
                LDSM_X4(bh[4 * q], bh[4 * q + 1], bh[4 * q + 2], bh[4 * q + 3],
                        tBh + swz64((uint32_t)((wn * 32 + q * 16 + b_r) * 64 + (kk + b_c) * 2)));
            // A hi: 4 m-subtiles of 16 rows
#pragma unroll
            for (int mt = 0; mt < 4; mt++)
                LDSM_X4(a[4 * mt], a[4 * mt + 1], a[4 * mt + 2], a[4 * mt + 3],
                        tAh + swz64((uint32_t)((wm * 64 + mt * 16 + a_r) * 64 + (kk + a_c) * 2)));
            // pass 1: x2h * tmph
#pragma unroll
            for (int mt = 0; mt < 4; mt++)
#pragma unroll
                for (int nt = 0; nt < 4; nt++)
                    mma_fp16(c[mt][nt], a + 4 * mt, bh + 2 * nt);
            // A lo (reload over a)
#pragma unroll
            for (int mt = 0; mt < 4; mt++)
                LDSM_X4(a[4 * mt], a[4 * mt + 1], a[4 * mt + 2], a[4 * mt + 3],
                        tAl + swz64((uint32_t)((wm * 64 + mt * 16 + a_r) * 64 + (kk + a_c) * 2)));
            // pass 2: x2l * tmph
#pragma unroll
            for (int mt = 0; mt < 4; mt++)
#pragma unroll
                for (int nt = 0; nt < 4; nt++)
                    mma_fp16(c[mt][nt], a + 4 * mt, bh + 2 * nt);
        }
        __syncthreads();
    }

    // ---- Epilogue: direct f32 stores + bias
#pragma unroll
    for (int mt = 0; mt < 4; mt++)
#pragma unroll
        for (int nt = 0; nt < 4; nt++) {
            int n = wn * 32 + nt * 8 + (lane & 3) * 2;
            float2 bv = *reinterpret_cast<const float2*>(&bias[n]);
#pragma unroll
            for (int h = 0; h < 2; h++) {
                int m = wm * 64 + mt * 16 + (lane >> 2) + h * 8;
                size_t ob = ((size_t)bi * L_SEQ + m) * KOUT + n;
                float2 v;
                v.x = c[mt][nt][2 * h]     + bv.x;
                v.y = c[mt][nt][2 * h + 1] + bv.y;
                *reinterpret_cast<float2*>(&out[ob]) = v;
            }
        }
}

// ---------------------------------------------------------------------------
// Launch
// ---------------------------------------------------------------------------
extern "C" void kernel_launch(void* const* d_in, const int* in_sizes, int n_in,
                              void* d_out, int out_size)
{
    const float* x1   = (const float*)d_in[0];   // [8,256,512]
    const float* x2   = (const float*)d_in[1];   // [8,256,512]
    const float* w    = (const float*)d_in[2];   // [64,512,512]
    const float* bias = (const float*)d_in[3];   // [64]
    float* out = (float*)d_out;                  // [8,256,256,64]

    __half *a1h, *a1l, *x2h, *x2l;
    cudaGetSymbolAddress((void**)&a1h, g_a1h);
    cudaGetSymbolAddress((void**)&a1l, g_a1l);
    cudaGetSymbolAddress((void**)&x2h, g_x2h);
    cudaGetSymbolAddress((void**)&x2l, g_x2l);

    cudaFuncSetAttribute(gemm1_mma, cudaFuncAttributeMaxDynamicSharedMemorySize, G1_SMEM);
    cudaFuncSetAttribute(gemm2_mma, cudaFuncAttributeMaxDynamicSharedMemorySize, G2_SMEM);

    int n4 = M1 * D1 / 4;
    cvt_split_kernel<<<(n4 + 255) / 256, 256>>>(x1, a1h, a1l, n4);
    cvt_split_kernel<<<(n4 + 255) / 256, 256>>>(x2, x2h, x2l, n4);
    cvt_w_kernel<<<dim3(16, 16, 64), dim3(32, 8)>>>(w);

    gemm1_mma<<<dim3(16, 4, 64), 256, G1_SMEM>>>();
    gemm2_mma<<<2048, 256, G2_SMEM>>>(bias, out);
}

// round 9
// speedup vs baseline: 6.8975x; 1.5722x over previous
#include <cuda_runtime.h>
#include <cuda_fp16.h>
#include <cstdint>

// ---------------------------------------------------------------------------
// Problem dims
// ---------------------------------------------------------------------------
#define B_BATCH 8
#define L_SEQ   256
#define D1      512
#define D2      512
#define KOUT    64
#define M1      (B_BATCH * L_SEQ)   // 2048 rows (b,i)

// ---------------------------------------------------------------------------
// Helpers (sm_80-era ISA only — harness PTX target is sm_103 without 'a')
// ---------------------------------------------------------------------------
__device__ __forceinline__ uint32_t smem_u32(const void* p) {
    uint32_t a;
    asm("{ .reg .u64 t; cvta.to.shared.u64 t, %1; cvt.u32.u64 %0, t; }"
        : "=r"(a) : "l"(p));
    return a;
}

__device__ __forceinline__ uint32_t swz128(uint32_t off) {  // 128B-row swizzle
    return off ^ ((off >> 3) & 0x70);
}
__device__ __forceinline__ uint32_t swz64(uint32_t off) {   // 64B-row swizzle
    return off ^ ((off >> 3) & 0x30);
}

#define LDSM_X4(r0, r1, r2, r3, addr) \
    asm volatile("ldmatrix.sync.aligned.m8n8.x4.shared.b16 {%0,%1,%2,%3}, [%4];" \
        : "=r"(r0), "=r"(r1), "=r"(r2), "=r"(r3) : "r"(addr))

#define CP_ASYNC16(smem_addr, gptr) \
    asm volatile("cp.async.cg.shared.global [%0], [%1], 16;" \
        :: "r"(smem_addr), "l"(gptr))

#define CP_COMMIT()  asm volatile("cp.async.commit_group;" ::: "memory")
#define CP_WAIT(N)   asm volatile("cp.async.wait_group %0;" :: "n"(N) : "memory")

__device__ __forceinline__ void mma_fp16(float* c, const uint32_t* a, const uint32_t* b) {
    asm volatile(
        "mma.sync.aligned.m16n8k16.row.col.f32.f16.f16.f32 "
        "{%0,%1,%2,%3}, {%4,%5,%6,%7}, {%8,%9}, {%0,%1,%2,%3};"
        : "+f"(c[0]), "+f"(c[1]), "+f"(c[2]), "+f"(c[3])
        : "r"(a[0]), "r"(a[1]), "r"(a[2]), "r"(a[3]), "r"(b[0]), "r"(b[1]));
}

__device__ __forceinline__ uint32_t pack2h(float a, float b) {
    __half2 t = __floats2half2_rn(a, b);
    return *reinterpret_cast<uint32_t*>(&t);
}

// ---------------------------------------------------------------------------
// Scratch
// ---------------------------------------------------------------------------
__device__ __align__(256) __half g_x1[(size_t)M1 * D1];             // X1 fp16
__device__ __align__(256) __half g_x2[(size_t)M1 * D2];             // X2 fp16
__device__ __align__(256) __half g_wt[(size_t)KOUT * D2 * D1];      // W^T fp16 [k][q][p]
__device__ __align__(256) __half g_t[(size_t)M1 * KOUT * D2];       // tmp fp16 [m][k][q]

// ---------------------------------------------------------------------------
// Conversion kernels
// ---------------------------------------------------------------------------
__global__ __launch_bounds__(256) void cvt_fp16_kernel(
    const float* __restrict__ in, __half* __restrict__ out16, int n4)
{
    int i = blockIdx.x * 256 + threadIdx.x;
    if (i >= n4) return;
    float4 v = reinterpret_cast<const float4*>(in)[i];
    reinterpret_cast<__half2*>(out16)[2 * i] =
        __halves2half2(__float2half_rn(v.x), __float2half_rn(v.y));
    reinterpret_cast<__half2*>(out16)[2 * i + 1] =
        __halves2half2(__float2half_rn(v.z), __float2half_rn(v.w));
}

// W[k][p][q] -> Wt[k][q][p] fp16.  grid (16,16,64), block (32,8)
__global__ void cvt_w_kernel(const float* __restrict__ W)
{
    __shared__ float t[32][33];
    int k  = blockIdx.z;
    int q0 = blockIdx.x * 32;
    int p0 = blockIdx.y * 32;
    const float* Wk = W + (size_t)k * D1 * D2;
    int tx = threadIdx.x, ty = threadIdx.y;
#pragma unroll
    for (int i = 0; i < 4; i++)
        t[ty + 8 * i][tx] = Wk[(size_t)(p0 + ty + 8 * i) * D2 + q0 + tx];
    __syncthreads();
#pragma unroll
    for (int i = 0; i < 4; i++) {
        size_t o = (size_t)k * D2 * D1 + (size_t)(q0 + ty + 8 * i) * D1 + p0 + tx;
        g_wt[o] = __float2half_rn(t[tx][ty + 8 * i]);
    }
}

// ---------------------------------------------------------------------------
// Tile copies: gmem pitch 512 halves -> swizzled SMEM
// ---------------------------------------------------------------------------
template <int ROWS>   // 128B rows (64 halves), SW128
__device__ __forceinline__ void tile_cp64(
    const __half* __restrict__ g, uint32_t s, int tid)
{
#pragma unroll
    for (int idx = tid; idx < ROWS * 8; idx += 256) {
        int row = idx >> 3, u = idx & 7;
        CP_ASYNC16(s + swz128((uint32_t)(row * 128 + u * 16)),
                   g + (size_t)row * 512 + u * 8);
    }
}

template <int ROWS>   // 64B rows (32 halves), SW64
__device__ __forceinline__ void tile_cp32(
    const __half* __restrict__ g, uint32_t s, int tid)
{
#pragma unroll
    for (int idx = tid; idx < ROWS * 4; idx += 256) {
        int row = idx >> 2, u = idx & 3;
        CP_ASYNC16(s + swz64((uint32_t)(row * 64 + u * 16)),
                   g + (size_t)row * 512 + u * 8);
    }
}

// ---------------------------------------------------------------------------
// GEMM1: tmp[m, kb, q] = sum_p X1[m,p] * W[kb,p,q]    (single-pass fp16)
//   grid (16, 4, 64), block 256 (8 warps), 2 CTAs/SM.
//   Block tile 128(m) x 128(q), K=512 in 8 chunks of 64, 3-stage cp.async.
// SMEM stage (32 KB): A(16K) B(16K), 128B rows, SW128.
// Epilogue stages fp16 via padded SMEM.
// ---------------------------------------------------------------------------
#define G1_SLOT 32768
#define G1_SMEM (1024 + 3 * G1_SLOT)   // 99328 -> 2 CTAs/SM

__global__ __launch_bounds__(256, 2) void gemm1_mma(void)
{
    extern __shared__ char smem[];
    uint32_t sb = smem_u32(smem);
    const int tid = threadIdx.x, wid = tid >> 5, lane = tid & 31;
    const int m0 = blockIdx.x * 128, n0 = blockIdx.y * 128, kb = blockIdx.z;
    const int wm = wid & 3, wn = wid >> 2;       // warp tile 32(m) x 64(n)

    const __half* A = g_x1 + (size_t)m0 * D1;
    const __half* B = g_wt + ((size_t)kb * D2 + n0) * D1;

    float c[2][8][4];
#pragma unroll
    for (int i = 0; i < 2; i++)
#pragma unroll
        for (int j = 0; j < 8; j++)
#pragma unroll
            for (int e = 0; e < 4; e++) c[i][j][e] = 0.0f;

    const int a_r = lane & 15, a_c = (lane >> 4) * 8;
    const int b_r = ((lane >> 4) & 1) * 8 + (lane & 7), b_c = ((lane >> 3) & 1) * 8;

    // prologue: chunks 0,1 -> stages 0,1
#pragma unroll
    for (int s = 0; s < 2; s++) {
        uint32_t tb = sb + 1024 + s * G1_SLOT;
        tile_cp64<128>(A + s * 64, tb, tid);
        tile_cp64<128>(B + s * 64, tb + 16384, tid);
        CP_COMMIT();
    }

#pragma unroll 1
    for (int ch = 0; ch < 8; ch++) {
        if (ch + 2 < 8) { CP_WAIT(1); } else { CP_WAIT(0); }
        __syncthreads();
        if (ch + 2 < 8) {
            int p0 = (ch + 2) * 64;
            uint32_t tb = sb + 1024 + ((ch + 2) % 3) * G1_SLOT;
            tile_cp64<128>(A + p0, tb, tid);
            tile_cp64<128>(B + p0, tb + 16384, tid);
            CP_COMMIT();
        }

        uint32_t tb = sb + 1024 + (ch % 3) * G1_SLOT;
        uint32_t tA = tb, tB = tb + 16384;

#pragma unroll
        for (int kk = 0; kk < 64; kk += 16) {
            uint32_t a[8], b[16];
            LDSM_X4(a[0], a[1], a[2], a[3],
                    tA + swz128((uint32_t)((wm * 32 + a_r) * 128 + (kk + a_c) * 2)));
            LDSM_X4(a[4], a[5], a[6], a[7],
                    tA + swz128((uint32_t)((wm * 32 + 16 + a_r) * 128 + (kk + a_c) * 2)));
#pragma unroll
            for (int q = 0; q < 4; q++)
                LDSM_X4(b[4 * q], b[4 * q + 1], b[4 * q + 2], b[4 * q + 3],
                        tB + swz128((uint32_t)((wn * 64 + q * 16 + b_r) * 128 + (kk + b_c) * 2)));
#pragma unroll
            for (int mt = 0; mt < 2; mt++)
#pragma unroll
                for (int nt = 0; nt < 8; nt++)
                    mma_fp16(c[mt][nt], (mt ? a + 4 : a), b + 2 * nt);
        }
        __syncthreads();
    }

    // ---- Epilogue: stage fp16 in padded SMEM, then coalesced 16B stores
    char* Sh = smem + 1024;                    // [128][pitch 136 half] = 34 KB
#pragma unroll
    for (int mt = 0; mt < 2; mt++)
#pragma unroll
        for (int nt = 0; nt < 8; nt++)
#pragma unroll
            for (int h = 0; h < 2; h++) {
                int m = wm * 32 + mt * 16 + (lane >> 2) + h * 8;
                int n = wn * 64 + nt * 8 + (lane & 3) * 2;
                *reinterpret_cast<uint32_t*>(Sh + m * 272 + n * 2) =
                    pack2h(c[mt][nt][2 * h], c[mt][nt][2 * h + 1]);
            }
    __syncthreads();
#pragma unroll
    for (int idx = tid; idx < 1024; idx += 256) {
        int row = idx >> 3, u = idx & 7;
        size_t ob = (size_t)(m0 + row) * (KOUT * D2) + (size_t)kb * D2 + n0 + u * 16;
        *reinterpret_cast<uint4*>(&g_t[ob]) =
            *reinterpret_cast<const uint4*>(Sh + row * 272 + u * 32);
        *reinterpret_cast<uint4*>(&g_t[ob + 8]) =
            *reinterpret_cast<const uint4*>(Sh + row * 272 + u * 32 + 16);
    }
}

// ---------------------------------------------------------------------------
// GEMM2: out[bi, j, k'] = sum_q X2[b,j,q] * tmp[bi,k',q] + bias[k']
//   (single-pass fp16)
//   grid (2048), block 256 (8 warps), 2 CTAs/SM.
//   Block tile 256(j) x 64(k'), one block per bi. K=512 in 16 chunks of 32,
//   3-stage cp.async.
// SMEM stage (20 KB): A(16K) B(4K), 64B rows, SW64.
//   Warp tile 64(j) x 32(k').
// ---------------------------------------------------------------------------
#define G2_SLOT 20480
#define G2_SMEM (1024 + 3 * G2_SLOT)   // 62464 -> 2 CTAs/SM

__global__ __launch_bounds__(256, 2) void gemm2_mma(
    const float* __restrict__ bias, float* __restrict__ out)
{
    extern __shared__ char smem[];
    uint32_t sb = smem_u32(smem);
    const int tid = threadIdx.x, wid = tid >> 5, lane = tid & 31;
    const int bi = blockIdx.x;
    const int b  = bi >> 8;
    const int wm = wid & 3, wn = wid >> 2;       // warp tile 64(j) x 32(k')

    const __half* A = g_x2 + (size_t)b * L_SEQ * D2;
    const __half* B = g_t + (size_t)bi * KOUT * D2;

    float c[4][4][4];
#pragma unroll
    for (int i = 0; i < 4; i++)
#pragma unroll
        for (int j = 0; j < 4; j++)
#pragma unroll
            for (int e = 0; e < 4; e++) c[i][j][e] = 0.0f;

    const int a_r = lane & 15, a_c = (lane >> 4) * 8;
    const int b_r = ((lane >> 4) & 1) * 8 + (lane & 7), b_c = ((lane >> 3) & 1) * 8;

#pragma unroll
    for (int s = 0; s < 2; s++) {
        uint32_t tb = sb + 1024 + s * G2_SLOT;
        tile_cp32<256>(A + s * 32, tb, tid);
        tile_cp32<64>(B + s * 32, tb + 16384, tid);
        CP_COMMIT();
    }

#pragma unroll 1
    for (int ch = 0; ch < 16; ch++) {
        if (ch + 2 < 16) { CP_WAIT(1); } else { CP_WAIT(0); }
        __syncthreads();
        if (ch + 2 < 16) {
            int q0 = (ch + 2) * 32;
            uint32_t tb = sb + 1024 + ((ch + 2) % 3) * G2_SLOT;
            tile_cp32<256>(A + q0, tb, tid);
            tile_cp32<64>(B + q0, tb + 16384, tid);
            CP_COMMIT();
        }

        uint32_t tb = sb + 1024 + (ch % 3) * G2_SLOT;
        uint32_t tA = tb, tB = tb + 16384;

#pragma unroll
        for (int kk = 0; kk < 32; kk += 16) {
            uint32_t a[16], bh[8];
#pragma unroll
            for (int q = 0; q < 2; q++)
                LDSM_X4(bh[4 * q], bh[4 * q + 1], bh[4 * q + 2], bh[4 * q + 3],
                        tB + swz64((uint32_t)((wn * 32 + q * 16 + b_r) * 64 + (kk + b_c) * 2)));
#pragma unroll
            for (int mt = 0; mt < 4; mt++)
                LDSM_X4(a[4 * mt], a[4 * mt + 1], a[4 * mt + 2], a[4 * mt + 3],
                        tA + swz64((uint32_t)((wm * 64 + mt * 16 + a_r) * 64 + (kk + a_c) * 2)));
#pragma unroll
            for (int mt = 0; mt < 4; mt++)
#pragma unroll
                for (int nt = 0; nt < 4; nt++)
                    mma_fp16(c[mt][nt], a + 4 * mt, bh + 2 * nt);
        }
        __syncthreads();
    }

    // ---- Epilogue: direct f32 stores + bias
#pragma unroll
    for (int mt = 0; mt < 4; mt++)
#pragma unroll
        for (int nt = 0; nt < 4; nt++) {
            int n = wn * 32 + nt * 8 + (lane & 3) * 2;
            float2 bv = *reinterpret_cast<const float2*>(&bias[n]);
#pragma unroll
            for (int h = 0; h < 2; h++) {
                int m = wm * 64 + mt * 16 + (lane >> 2) + h * 8;
                size_t ob = ((size_t)bi * L_SEQ + m) * KOUT + n;
                float2 v;
                v.x = c[mt][nt][2 * h]     + bv.x;
                v.y = c[mt][nt][2 * h + 1] + bv.y;
                *reinterpret_cast<float2*>(&out[ob]) = v;
            }
        }
}

// ---------------------------------------------------------------------------
// Launch
// ---------------------------------------------------------------------------
extern "C" void kernel_launch(void* const* d_in, const int* in_sizes, int n_in,
                              void* d_out, int out_size)
{
    const float* x1   = (const float*)d_in[0];   // [8,256,512]
    const float* x2   = (const float*)d_in[1];   // [8,256,512]
    const float* w    = (const float*)d_in[2];   // [64,512,512]
    const float* bias = (const float*)d_in[3];   // [64]
    float* out = (float*)d_out;                  // [8,256,256,64]

    __half *x1h, *x2h;
    cudaGetSymbolAddress((void**)&x1h, g_x1);
    cudaGetSymbolAddress((void**)&x2h, g_x2);

    cudaFuncSetAttribute(gemm1_mma, cudaFuncAttributeMaxDynamicSharedMemorySize, G1_SMEM);
    cudaFuncSetAttribute(gemm2_mma, cudaFuncAttributeMaxDynamicSharedMemorySize, G2_SMEM);

    int n4 = M1 * D1 / 4;
    cvt_fp16_kernel<<<(n4 + 255) / 256, 256>>>(x1, x1h, n4);
    cvt_fp16_kernel<<<(n4 + 255) / 256, 256>>>(x2, x2h, n4);
    cvt_w_kernel<<<dim3(16, 16, 64), dim3(32, 8)>>>(w);

    gemm1_mma<<<dim3(16, 4, 64), 256, G1_SMEM>>>();
    gemm2_mma<<<2048, 256, G2_SMEM>>>(bias, out);
}

// round 10
// speedup vs baseline: 6.9330x; 1.0051x over previous
#include <cuda_runtime.h>
#include <cuda_fp16.h>
#include <cstdint>

// ---------------------------------------------------------------------------
// Problem dims
// ---------------------------------------------------------------------------
#define B_BATCH 8
#define L_SEQ   256
#define D1      512
#define D2      512
#define KOUT    64
#define M1      (B_BATCH * L_SEQ)   // 2048 rows (b,i)

// ---------------------------------------------------------------------------
// Helpers (sm_80-era ISA only — harness PTX target is sm_103 without 'a')
// ---------------------------------------------------------------------------
__device__ __forceinline__ uint32_t smem_u32(const void* p) {
    uint32_t a;
    asm("{ .reg .u64 t; cvta.to.shared.u64 t, %1; cvt.u32.u64 %0, t; }"
        : "=r"(a) : "l"(p));
    return a;
}

__device__ __forceinline__ uint32_t swz128(uint32_t off) {  // 128B-row swizzle
    return off ^ ((off >> 3) & 0x70);
}
__device__ __forceinline__ uint32_t swz64(uint32_t off) {   // 64B-row swizzle
    return off ^ ((off >> 3) & 0x30);
}

#define LDSM_X4(r0, r1, r2, r3, addr) \
    asm volatile("ldmatrix.sync.aligned.m8n8.x4.shared.b16 {%0,%1,%2,%3}, [%4];" \
        : "=r"(r0), "=r"(r1), "=r"(r2), "=r"(r3) : "r"(addr))

#define CP_ASYNC16(smem_addr, gptr) \
    asm volatile("cp.async.cg.shared.global [%0], [%1], 16;" \
        :: "r"(smem_addr), "l"(gptr))

#define CP_COMMIT()  asm volatile("cp.async.commit_group;" ::: "memory")
#define CP_WAIT(N)   asm volatile("cp.async.wait_group %0;" :: "n"(N) : "memory")

__device__ __forceinline__ void mma_fp16(float* c, const uint32_t* a, const uint32_t* b) {
    asm volatile(
        "mma.sync.aligned.m16n8k16.row.col.f32.f16.f16.f32 "
        "{%0,%1,%2,%3}, {%4,%5,%6,%7}, {%8,%9}, {%0,%1,%2,%3};"
        : "+f"(c[0]), "+f"(c[1]), "+f"(c[2]), "+f"(c[3])
        : "r"(a[0]), "r"(a[1]), "r"(a[2]), "r"(a[3]), "r"(b[0]), "r"(b[1]));
}

__device__ __forceinline__ uint32_t pack2h(float a, float b) {
    __half2 t = __floats2half2_rn(a, b);
    return *reinterpret_cast<uint32_t*>(&t);
}

// ---------------------------------------------------------------------------
// Scratch
// ---------------------------------------------------------------------------
__device__ __align__(256) __half g_x1[(size_t)M1 * D1];             // X1 fp16
__device__ __align__(256) __half g_x2[(size_t)M1 * D2];             // X2 fp16
__device__ __align__(256) __half g_wt[(size_t)KOUT * D2 * D1];      // W^T fp16 [k][q][p]
__device__ __align__(256) __half g_t[(size_t)M1 * KOUT * D2];       // tmp fp16 [m][k][q]

// ---------------------------------------------------------------------------
// Conversion kernels
// ---------------------------------------------------------------------------
__global__ __launch_bounds__(256) void cvt_fp16_kernel(
    const float* __restrict__ x1, const float* __restrict__ x2, int n4)
{
    int i = blockIdx.x * 256 + threadIdx.x;
    if (i >= n4) return;
    float4 v = reinterpret_cast<const float4*>(x1)[i];
    reinterpret_cast<__half2*>(g_x1)[2 * i] =
        __halves2half2(__float2half_rn(v.x), __float2half_rn(v.y));
    reinterpret_cast<__half2*>(g_x1)[2 * i + 1] =
        __halves2half2(__float2half_rn(v.z), __float2half_rn(v.w));
    float4 w = reinterpret_cast<const float4*>(x2)[i];
    reinterpret_cast<__half2*>(g_x2)[2 * i] =
        __halves2half2(__float2half_rn(w.x), __float2half_rn(w.y));
    reinterpret_cast<__half2*>(g_x2)[2 * i + 1] =
        __halves2half2(__float2half_rn(w.z), __float2half_rn(w.w));
}

// W[k][p][q] -> Wt[k][q][p] fp16.  grid (16,16,64), block (32,8)
__global__ void cvt_w_kernel(const float* __restrict__ W)
{
    __shared__ float t[32][33];
    int k  = blockIdx.z;
    int q0 = blockIdx.x * 32;
    int p0 = blockIdx.y * 32;
    const float* Wk = W + (size_t)k * D1 * D2;
    int tx = threadIdx.x, ty = threadIdx.y;
#pragma unroll
    for (int i = 0; i < 4; i++)
        t[ty + 8 * i][tx] = Wk[(size_t)(p0 + ty + 8 * i) * D2 + q0 + tx];
    __syncthreads();
#pragma unroll
    for (int i = 0; i < 4; i++) {
        size_t o = (size_t)k * D2 * D1 + (size_t)(q0 + ty + 8 * i) * D1 + p0 + tx;
        g_wt[o] = __float2half_rn(t[tx][ty + 8 * i]);
    }
}

// ---------------------------------------------------------------------------
// Tile copies: gmem pitch 512 halves -> swizzled SMEM
// ---------------------------------------------------------------------------
template <int ROWS>   // 128B rows (64 halves), SW128
__device__ __forceinline__ void tile_cp64(
    const __half* __restrict__ g, uint32_t s, int tid)
{
#pragma unroll
    for (int idx = tid; idx < ROWS * 8; idx += 256) {
        int row = idx >> 3, u = idx & 7;
        CP_ASYNC16(s + swz128((uint32_t)(row * 128 + u * 16)),
                   g + (size_t)row * 512 + u * 8);
    }
}

template <int ROWS>   // 64B rows (32 halves), SW64
__device__ __forceinline__ void tile_cp32(
    const __half* __restrict__ g, uint32_t s, int tid)
{
#pragma unroll
    for (int idx = tid; idx < ROWS * 4; idx += 256) {
        int row = idx >> 2, u = idx & 3;
        CP_ASYNC16(s + swz64((uint32_t)(row * 64 + u * 16)),
                   g + (size_t)row * 512 + u * 8);
    }
}

// ---------------------------------------------------------------------------
// GEMM1: tmp[m, kb, q] = sum_p X1[m,p] * W[kb,p,q]    (single-pass fp16)
//   grid (16, 4, 64), block 256 (8 warps), 2 CTAs/SM.
//   Block tile 128(m) x 128(q), K=512 in 8 chunks of 64, 3-stage cp.async,
//   register double-buffered fragment pipeline in the k-loop.
// SMEM stage (32 KB): A(16K) B(16K), 128B rows, SW128.
// ---------------------------------------------------------------------------
#define G1_SLOT 32768
#define G1_SMEM (1024 + 3 * G1_SLOT)   // 99328 -> 2 CTAs/SM

__global__ __launch_bounds__(256, 2) void gemm1_mma(void)
{
    extern __shared__ char smem[];
    uint32_t sb = smem_u32(smem);
    const int tid = threadIdx.x, wid = tid >> 5, lane = tid & 31;
    const int m0 = blockIdx.x * 128, n0 = blockIdx.y * 128, kb = blockIdx.z;
    const int wm = wid & 3, wn = wid >> 2;       // warp tile 32(m) x 64(n)

    const __half* A = g_x1 + (size_t)m0 * D1;
    const __half* B = g_wt + ((size_t)kb * D2 + n0) * D1;

    float c[2][8][4];
#pragma unroll
    for (int i = 0; i < 2; i++)
#pragma unroll
        for (int j = 0; j < 8; j++)
#pragma unroll
            for (int e = 0; e < 4; e++) c[i][j][e] = 0.0f;

    const int a_r = lane & 15, a_c = (lane >> 4) * 8;
    const int b_r = ((lane >> 4) & 1) * 8 + (lane & 7), b_c = ((lane >> 3) & 1) * 8;

    // prologue: chunks 0,1 -> stages 0,1
#pragma unroll
    for (int s = 0; s < 2; s++) {
        uint32_t tb = sb + 1024 + s * G1_SLOT;
        tile_cp64<128>(A + s * 64, tb, tid);
        tile_cp64<128>(B + s * 64, tb + 16384, tid);
        CP_COMMIT();
    }

#pragma unroll 1
    for (int ch = 0; ch < 8; ch++) {
        if (ch + 2 < 8) { CP_WAIT(1); } else { CP_WAIT(0); }
        __syncthreads();
        if (ch + 2 < 8) {
            int p0 = (ch + 2) * 64;
            uint32_t tb = sb + 1024 + ((ch + 2) % 3) * G1_SLOT;
            tile_cp64<128>(A + p0, tb, tid);
            tile_cp64<128>(B + p0, tb + 16384, tid);
            CP_COMMIT();
        }

        uint32_t tb = sb + 1024 + (ch % 3) * G1_SLOT;
        uint32_t tA = tb, tB = tb + 16384;

        uint32_t a[2][8], b[2][16];
        // preload kk=0 fragments
        LDSM_X4(a[0][0], a[0][1], a[0][2], a[0][3],
                tA + swz128((uint32_t)((wm * 32 + a_r) * 128 + a_c * 2)));
        LDSM_X4(a[0][4], a[0][5], a[0][6], a[0][7],
                tA + swz128((uint32_t)((wm * 32 + 16 + a_r) * 128 + a_c * 2)));
#pragma unroll
        for (int q = 0; q < 4; q++)
            LDSM_X4(b[0][4 * q], b[0][4 * q + 1], b[0][4 * q + 2], b[0][4 * q + 3],
                    tB + swz128((uint32_t)((wn * 64 + q * 16 + b_r) * 128 + b_c * 2)));

#pragma unroll
        for (int ks = 0; ks < 4; ks++) {
            const int cur = ks & 1, nxt = cur ^ 1;
            if (ks < 3) {
                const int kk = (ks + 1) * 16;
                LDSM_X4(a[nxt][0], a[nxt][1], a[nxt][2], a[nxt][3],
                        tA + swz128((uint32_t)((wm * 32 + a_r) * 128 + (kk + a_c) * 2)));
                LDSM_X4(a[nxt][4], a[nxt][5], a[nxt][6], a[nxt][7],
                        tA + swz128((uint32_t)((wm * 32 + 16 + a_r) * 128 + (kk + a_c) * 2)));
#pragma unroll
                for (int q = 0; q < 4; q++)
                    LDSM_X4(b[nxt][4 * q], b[nxt][4 * q + 1], b[nxt][4 * q + 2], b[nxt][4 * q + 3],
                            tB + swz128((uint32_t)((wn * 64 + q * 16 + b_r) * 128 + (kk + b_c) * 2)));
            }
#pragma unroll
            for (int mt = 0; mt < 2; mt++)
#pragma unroll
                for (int nt = 0; nt < 8; nt++)
                    mma_fp16(c[mt][nt], (mt ? a[cur] + 4 : a[cur]), b[cur] + 2 * nt);
        }
        __syncthreads();
    }

    // ---- Epilogue: stage fp16 in padded SMEM, then coalesced 16B stores
    char* Sh = smem + 1024;                    // [128][pitch 136 half] = 34 KB
#pragma unroll
    for (int mt = 0; mt < 2; mt++)
#pragma unroll
        for (int nt = 0; nt < 8; nt++)
#pragma unroll
            for (int h = 0; h < 2; h++) {
                int m = wm * 32 + mt * 16 + (lane >> 2) + h * 8;
                int n = wn * 64 + nt * 8 + (lane & 3) * 2;
                *reinterpret_cast<uint32_t*>(Sh + m * 272 + n * 2) =
                    pack2h(c[mt][nt][2 * h], c[mt][nt][2 * h + 1]);
            }
    __syncthreads();
#pragma unroll
    for (int idx = tid; idx < 1024; idx += 256) {
        int row = idx >> 3, u = idx & 7;
        size_t ob = (size_t)(m0 + row) * (KOUT * D2) + (size_t)kb * D2 + n0 + u * 16;
        *reinterpret_cast<uint4*>(&g_t[ob]) =
            *reinterpret_cast<const uint4*>(Sh + row * 272 + u * 32);
        *reinterpret_cast<uint4*>(&g_t[ob + 8]) =
            *reinterpret_cast<const uint4*>(Sh + row * 272 + u * 32 + 16);
    }
}

// ---------------------------------------------------------------------------
// GEMM2: out[bi, j, k'] = sum_q X2[b,j,q] * tmp[bi,k',q] + bias[k']
//   (single-pass fp16)
//   grid (2048), block 256 (8 warps), 2 CTAs/SM.
//   Block tile 256(j) x 64(k'), one block per bi. K=512 in 16 chunks of 32,
//   3-stage cp.async, register double-buffered fragments.
// SMEM stage (20 KB): A(16K) B(4K), 64B rows, SW64.
//   Warp tile 64(j) x 32(k').
// ---------------------------------------------------------------------------
#define G2_SLOT 20480
#define G2_SMEM (1024 + 3 * G2_SLOT)   // 62464 -> 2 CTAs/SM

__global__ __launch_bounds__(256, 2) void gemm2_mma(
    const float* __restrict__ bias, float* __restrict__ out)
{
    extern __shared__ char smem[];
    uint32_t sb = smem_u32(smem);
    const int tid = threadIdx.x, wid = tid >> 5, lane = tid & 31;
    const int bi = blockIdx.x;
    const int b  = bi >> 8;
    const int wm = wid & 3, wn = wid >> 2;       // warp tile 64(j) x 32(k')

    const __half* A = g_x2 + (size_t)b * L_SEQ * D2;
    const __half* B = g_t + (size_t)bi * KOUT * D2;

    float c[4][4][4];
#pragma unroll
    for (int i = 0; i < 4; i++)
#pragma unroll
        for (int j = 0; j < 4; j++)
#pragma unroll
            for (int e = 0; e < 4; e++) c[i][j][e] = 0.0f;

    const int a_r = lane & 15, a_c = (lane >> 4) * 8;
    const int b_r = ((lane >> 4) & 1) * 8 + (lane & 7), b_c = ((lane >> 3) & 1) * 8;

#pragma unroll
    for (int s = 0; s < 2; s++) {
        uint32_t tb = sb + 1024 + s * G2_SLOT;
        tile_cp32<256>(A + s * 32, tb, tid);
        tile_cp32<64>(B + s * 32, tb + 16384, tid);
        CP_COMMIT();
    }

#pragma unroll 1
    for (int ch = 0; ch < 16; ch++) {
        if (ch + 2 < 16) { CP_WAIT(1); } else { CP_WAIT(0); }
        __syncthreads();
        if (ch + 2 < 16) {
            int q0 = (ch + 2) * 32;
            uint32_t tb = sb + 1024 + ((ch + 2) % 3) * G2_SLOT;
            tile_cp32<256>(A + q0, tb, tid);
            tile_cp32<64>(B + q0, tb + 16384, tid);
            CP_COMMIT();
        }

        uint32_t tb = sb + 1024 + (ch % 3) * G2_SLOT;
        uint32_t tA = tb, tB = tb + 16384;

        uint32_t a[2][16], bh[2][8];
        // preload kk=0 fragments
#pragma unroll
        for (int q = 0; q < 2; q++)
            LDSM_X4(bh[0][4 * q], bh[0][4 * q + 1], bh[0][4 * q + 2], bh[0][4 * q + 3],
                    tB + swz64((uint32_t)((wn * 32 + q * 16 + b_r) * 64 + b_c * 2)));
#pragma unroll
        for (int mt = 0; mt < 4; mt++)
            LDSM_X4(a[0][4 * mt], a[0][4 * mt + 1], a[0][4 * mt + 2], a[0][4 * mt + 3],
                    tA + swz64((uint32_t)((wm * 64 + mt * 16 + a_r) * 64 + a_c * 2)));

#pragma unroll
        for (int ks = 0; ks < 2; ks++) {
            const int cur = ks & 1, nxt = cur ^ 1;
            if (ks < 1) {
                const int kk = 16;
#pragma unroll
                for (int q = 0; q < 2; q++)
                    LDSM_X4(bh[nxt][4 * q], bh[nxt][4 * q + 1], bh[nxt][4 * q + 2], bh[nxt][4 * q + 3],
                            tB + swz64((uint32_t)((wn * 32 + q * 16 + b_r) * 64 + (kk + b_c) * 2)));
#pragma unroll
                for (int mt = 0; mt < 4; mt++)
                    LDSM_X4(a[nxt][4 * mt], a[nxt][4 * mt + 1], a[nxt][4 * mt + 2], a[nxt][4 * mt + 3],
                            tA + swz64((uint32_t)((wm * 64 + mt * 16 + a_r) * 64 + (kk + a_c) * 2)));
            }
#pragma unroll
            for (int mt = 0; mt < 4; mt++)
#pragma unroll
                for (int nt = 0; nt < 4; nt++)
                    mma_fp16(c[mt][nt], a[cur] + 4 * mt, bh[cur] + 2 * nt);
        }
        __syncthreads();
    }

    // ---- Epilogue: direct f32 stores + bias
#pragma unroll
    for (int mt = 0; mt < 4; mt++)
#pragma unroll
        for (int nt = 0; nt < 4; nt++) {
            int n = wn * 32 + nt * 8 + (lane & 3) * 2;
            float2 bv = *reinterpret_cast<const float2*>(&bias[n]);
#pragma unroll
            for (int h = 0; h < 2; h++) {
                int m = wm * 64 + mt * 16 + (lane >> 2) + h * 8;
                size_t ob = ((size_t)bi * L_SEQ + m) * KOUT + n;
                float2 v;
                v.x = c[mt][nt][2 * h]     + bv.x;
                v.y = c[mt][nt][2 * h + 1] + bv.y;
                *reinterpret_cast<float2*>(&out[ob]) = v;
            }
        }
}

// ---------------------------------------------------------------------------
// Launch
// ---------------------------------------------------------------------------
extern "C" void kernel_launch(void* const* d_in, const int* in_sizes, int n_in,
                              void* d_out, int out_size)
{
    const float* x1   = (const float*)d_in[0];   // [8,256,512]
    const float* x2   = (const float*)d_in[1];   // [8,256,512]
    const float* w    = (const float*)d_in[2];   // [64,512,512]
    const float* bias = (const float*)d_in[3];   // [64]
    float* out = (float*)d_out;                  // [8,256,256,64]

    cudaFuncSetAttribute(gemm1_mma, cudaFuncAttributeMaxDynamicSharedMemorySize, G1_SMEM);
    cudaFuncSetAttribute(gemm2_mma, cudaFuncAttributeMaxDynamicSharedMemorySize, G2_SMEM);

    int n4 = M1 * D1 / 4;
    cvt_fp16_kernel<<<(n4 + 255) / 256, 256>>>(x1, x2, n4);
    cvt_w_kernel<<<dim3(16, 16, 64), dim3(32, 8)>>>(w);

    gemm1_mma<<<dim3(16, 4, 64), 256, G1_SMEM>>>();
    gemm2_mma<<<2048, 256, G2_SMEM>>>(bias, out);
}

// round 11
// speedup vs baseline: 6.9432x; 1.0015x over previous
#include <cuda_runtime.h>
#include <cuda_fp16.h>
#include <cstdint>

// ---------------------------------------------------------------------------
// Problem dims
// ---------------------------------------------------------------------------
#define B_BATCH 8
#define L_SEQ   256
#define D1      512
#define D2      512
#define KOUT    64
#define M1      (B_BATCH * L_SEQ)   // 2048 rows (b,i)

// ---------------------------------------------------------------------------
// Helpers (sm_80-era ISA only — harness PTX target is sm_103 without 'a')
// ---------------------------------------------------------------------------
__device__ __forceinline__ uint32_t smem_u32(const void* p) {
    uint32_t a;
    asm("{ .reg .u64 t; cvta.to.shared.u64 t, %1; cvt.u32.u64 %0, t; }"
        : "=r"(a) : "l"(p));
    return a;
}

__device__ __forceinline__ uint32_t swz128(uint32_t off) {  // 128B-row swizzle
    return off ^ ((off >> 3) & 0x70);
}

#define LDSM_X4(r0, r1, r2, r3, addr) \
    asm volatile("ldmatrix.sync.aligned.m8n8.x4.shared.b16 {%0,%1,%2,%3}, [%4];" \
        : "=r"(r0), "=r"(r1), "=r"(r2), "=r"(r3) : "r"(addr))

#define CP_ASYNC16(smem_addr, gptr) \
    asm volatile("cp.async.cg.shared.global [%0], [%1], 16;" \
        :: "r"(smem_addr), "l"(gptr))

#define CP_COMMIT()  asm volatile("cp.async.commit_group;" ::: "memory")
#define CP_WAIT(N)   asm volatile("cp.async.wait_group %0;" :: "n"(N) : "memory")

__device__ __forceinline__ void mma_fp16(float* c, const uint32_t* a, const uint32_t* b) {
    asm volatile(
        "mma.sync.aligned.m16n8k16.row.col.f32.f16.f16.f32 "
        "{%0,%1,%2,%3}, {%4,%5,%6,%7}, {%8,%9}, {%0,%1,%2,%3};"
        : "+f"(c[0]), "+f"(c[1]), "+f"(c[2]), "+f"(c[3])
        : "r"(a[0]), "r"(a[1]), "r"(a[2]), "r"(a[3]), "r"(b[0]), "r"(b[1]));
}

__device__ __forceinline__ uint32_t pack2h(float a, float b) {
    __half2 t = __floats2half2_rn(a, b);
    return *reinterpret_cast<uint32_t*>(&t);
}

// ---------------------------------------------------------------------------
// Scratch
// ---------------------------------------------------------------------------
__device__ __align__(256) __half g_x1[(size_t)M1 * D1];             // X1 fp16
__device__ __align__(256) __half g_x2[(size_t)M1 * D2];             // X2 fp16
__device__ __align__(256) __half g_wt[(size_t)KOUT * D2 * D1];      // W^T fp16 [k][q][p]
__device__ __align__(256) __half g_t[(size_t)M1 * KOUT * D2];       // tmp fp16 [m][k][q]

// ---------------------------------------------------------------------------
// Conversion kernels
// ---------------------------------------------------------------------------
__global__ __launch_bounds__(256) void cvt_fp16_kernel(
    const float* __restrict__ x1, const float* __restrict__ x2, int n4)
{
    int i = blockIdx.x * 256 + threadIdx.x;
    if (i >= n4) return;
    float4 v = reinterpret_cast<const float4*>(x1)[i];
    reinterpret_cast<__half2*>(g_x1)[2 * i] =
        __halves2half2(__float2half_rn(v.x), __float2half_rn(v.y));
    reinterpret_cast<__half2*>(g_x1)[2 * i + 1] =
        __halves2half2(__float2half_rn(v.z), __float2half_rn(v.w));
    float4 w = reinterpret_cast<const float4*>(x2)[i];
    reinterpret_cast<__half2*>(g_x2)[2 * i] =
        __halves2half2(__float2half_rn(w.x), __float2half_rn(w.y));
    reinterpret_cast<__half2*>(g_x2)[2 * i + 1] =
        __halves2half2(__float2half_rn(w.z), __float2half_rn(w.w));
}

// W[k][p][q] -> Wt[k][q][p] fp16.  grid (16,16,64), block (32,8)
__global__ void cvt_w_kernel(const float* __restrict__ W)
{
    __shared__ float t[32][33];
    int k  = blockIdx.z;
    int q0 = blockIdx.x * 32;
    int p0 = blockIdx.y * 32;
    const float* Wk = W + (size_t)k * D1 * D2;
    int tx = threadIdx.x, ty = threadIdx.y;
#pragma unroll
    for (int i = 0; i < 4; i++)
        t[ty + 8 * i][tx] = Wk[(size_t)(p0 + ty + 8 * i) * D2 + q0 + tx];
    __syncthreads();
#pragma unroll
    for (int i = 0; i < 4; i++) {
        size_t o = (size_t)k * D2 * D1 + (size_t)(q0 + ty + 8 * i) * D1 + p0 + tx;
        g_wt[o] = __float2half_rn(t[tx][ty + 8 * i]);
    }
}

// ---------------------------------------------------------------------------
// Tile copy: ROWS rows x 64 halves (128B rows), gmem pitch 512, SW128 smem
// ---------------------------------------------------------------------------
template <int ROWS>
__device__ __forceinline__ void tile_cp64(
    const __half* __restrict__ g, uint32_t s, int tid)
{
#pragma unroll
    for (int idx = tid; idx < ROWS * 8; idx += 256) {
        int row = idx >> 3, u = idx & 7;
        CP_ASYNC16(s + swz128((uint32_t)(row * 128 + u * 16)),
                   g + (size_t)row * 512 + u * 8);
    }
}

// ---------------------------------------------------------------------------
// GEMM1: tmp[m, kb, q] = sum_p X1[m,p] * W[kb,p,q]    (single-pass fp16)
//   grid (16, 2, 64), block 256 (8 warps), 1 CTA/SM (high regs).
//   Block tile 128(m) x 256(n); warp tile 64x64 (2x4 warp grid).
//   K=512 in 8 chunks of 64, 3-stage cp.async.
// SMEM stage (48 KB): A(16K: 128x64h) B(32K: 256x64h), SW128.
// ---------------------------------------------------------------------------
#define G1_SLOT 49152
#define G1_SMEM (1024 + 3 * G1_SLOT)   // 148480

__global__ __launch_bounds__(256, 1) void gemm1_mma(void)
{
    extern __shared__ char smem[];
    uint32_t sb = smem_u32(smem);
    const int tid = threadIdx.x, wid = tid >> 5, lane = tid & 31;
    const int m0 = blockIdx.x * 128, n0 = blockIdx.y * 256, kb = blockIdx.z;
    const int wm = wid & 1, wn = wid >> 1;       // warp tile 64(m) x 64(n)

    const __half* A = g_x1 + (size_t)m0 * D1;
    const __half* B = g_wt + ((size_t)kb * D2 + n0) * D1;

    float c[4][8][4];
#pragma unroll
    for (int i = 0; i < 4; i++)
#pragma unroll
        for (int j = 0; j < 8; j++)
#pragma unroll
            for (int e = 0; e < 4; e++) c[i][j][e] = 0.0f;

    const int a_r = lane & 15, a_c = (lane >> 4) * 8;
    const int b_r = ((lane >> 4) & 1) * 8 + (lane & 7), b_c = ((lane >> 3) & 1) * 8;

    // prologue: chunks 0,1 -> stages 0,1
#pragma unroll
    for (int s = 0; s < 2; s++) {
        uint32_t tb = sb + 1024 + s * G1_SLOT;
        tile_cp64<128>(A + s * 64, tb, tid);
        tile_cp64<256>(B + s * 64, tb + 16384, tid);
        CP_COMMIT();
    }

#pragma unroll 1
    for (int ch = 0; ch < 8; ch++) {
        if (ch + 2 < 8) { CP_WAIT(1); } else { CP_WAIT(0); }
        __syncthreads();
        if (ch + 2 < 8) {
            int p0 = (ch + 2) * 64;
            uint32_t tb = sb + 1024 + ((ch + 2) % 3) * G1_SLOT;
            tile_cp64<128>(A + p0, tb, tid);
            tile_cp64<256>(B + p0, tb + 16384, tid);
            CP_COMMIT();
        }

        uint32_t tb = sb + 1024 + (ch % 3) * G1_SLOT;
        uint32_t tA = tb, tB = tb + 16384;

#pragma unroll
        for (int kk = 0; kk < 64; kk += 16) {
            uint32_t a[16], b[16];
#pragma unroll
            for (int mt = 0; mt < 4; mt++)
                LDSM_X4(a[4 * mt], a[4 * mt + 1], a[4 * mt + 2], a[4 * mt + 3],
                        tA + swz128((uint32_t)((wm * 64 + mt * 16 + a_r) * 128 + (kk + a_c) * 2)));
#pragma unroll
            for (int q = 0; q < 4; q++)
                LDSM_X4(b[4 * q], b[4 * q + 1], b[4 * q + 2], b[4 * q + 3],
                        tB + swz128((uint32_t)((wn * 64 + q * 16 + b_r) * 128 + (kk + b_c) * 2)));
#pragma unroll
            for (int mt = 0; mt < 4; mt++)
#pragma unroll
                for (int nt = 0; nt < 8; nt++)
                    mma_fp16(c[mt][nt], a + 4 * mt, b + 2 * nt);
        }
        __syncthreads();
    }

    // ---- Epilogue: stage fp16 in padded SMEM, then coalesced 16B stores
    // layout: [128 rows][pitch 264 halves = 528B]  (67.6 KB, fits in smem)
    char* Sh = smem + 1024;
#pragma unroll
    for (int mt = 0; mt < 4; mt++)
#pragma unroll
        for (int nt = 0; nt < 8; nt++)
#pragma unroll
            for (int h = 0; h < 2; h++) {
                int m = wm * 64 + mt * 16 + (lane >> 2) + h * 8;
                int n = wn * 64 + nt * 8 + (lane & 3) * 2;
                *reinterpret_cast<uint32_t*>(Sh + m * 528 + n * 2) =
                    pack2h(c[mt][nt][2 * h], c[mt][nt][2 * h + 1]);
            }
    __syncthreads();
    // 128 rows x 256 halves = 128 x 32 uint4
#pragma unroll
    for (int idx = tid; idx < 4096; idx += 256) {
        int row = idx >> 5, u = idx & 31;
        size_t ob = (size_t)(m0 + row) * (KOUT * D2) + (size_t)kb * D2 + n0 + u * 8;
        *reinterpret_cast<uint4*>(&g_t[ob]) =
            *reinterpret_cast<const uint4*>(Sh + row * 528 + u * 16);
    }
}

// ---------------------------------------------------------------------------
// GEMM2: out[bi, j, k'] = sum_q X2[b,j,q] * tmp[bi,k',q] + bias[k']
//   (single-pass fp16)
//   grid (2048), block 256 (8 warps), 2 CTAs/SM.
//   Block tile 256(j) x 64(k'), one block per bi. K=512 in 8 chunks of 64,
//   2-stage cp.async.  Warp tile 64(j) x 32(k').
// SMEM stage (40 KB): A(32K: 256x64h) B(8K: 64x64h), SW128.
// ---------------------------------------------------------------------------
#define G2_SLOT 40960
#define G2_SMEM (1024 + 2 * G2_SLOT)   // 82944 -> 2 CTAs/SM

__global__ __launch_bounds__(256, 2) void gemm2_mma(
    const float* __restrict__ bias, float* __restrict__ out)
{
    extern __shared__ char smem[];
    uint32_t sb = smem_u32(smem);
    const int tid = threadIdx.x, wid = tid >> 5, lane = tid & 31;
    const int bi = blockIdx.x;
    const int b  = bi >> 8;
    const int wm = wid & 3, wn = wid >> 2;       // warp tile 64(j) x 32(k')

    const __half* A = g_x2 + (size_t)b * L_SEQ * D2;
    const __half* B = g_t + (size_t)bi * KOUT * D2;

    float c[4][4][4];
#pragma unroll
    for (int i = 0; i < 4; i++)
#pragma unroll
        for (int j = 0; j < 4; j++)
#pragma unroll
            for (int e = 0; e < 4; e++) c[i][j][e] = 0.0f;

    const int a_r = lane & 15, a_c = (lane >> 4) * 8;
    const int b_r = ((lane >> 4) & 1) * 8 + (lane & 7), b_c = ((lane >> 3) & 1) * 8;

    // prologue: chunk 0 -> stage 0
    {
        uint32_t tb = sb + 1024;
        tile_cp64<256>(A, tb, tid);
        tile_cp64<64>(B, tb + 32768, tid);
        CP_COMMIT();
    }

#pragma unroll 1
    for (int ch = 0; ch < 8; ch++) {
        if (ch < 7) {
            int q0 = (ch + 1) * 64;
            uint32_t tb = sb + 1024 + ((ch + 1) & 1) * G2_SLOT;
            tile_cp64<256>(A + q0, tb, tid);
            tile_cp64<64>(B + q0, tb + 32768, tid);
            CP_COMMIT();
            CP_WAIT(1);
        } else {
            CP_WAIT(0);
        }
        __syncthreads();

        uint32_t tb = sb + 1024 + (ch & 1) * G2_SLOT;
        uint32_t tA = tb, tB = tb + 32768;

#pragma unroll
        for (int kk = 0; kk < 64; kk += 16) {
            uint32_t a[16], bh[8];
#pragma unroll
            for (int q = 0; q < 2; q++)
                LDSM_X4(bh[4 * q], bh[4 * q + 1], bh[4 * q + 2], bh[4 * q + 3],
                        tB + swz128((uint32_t)((wn * 32 + q * 16 + b_r) * 128 + (kk + b_c) * 2)));
#pragma unroll
            for (int mt = 0; mt < 4; mt++)
                LDSM_X4(a[4 * mt], a[4 * mt + 1], a[4 * mt + 2], a[4 * mt + 3],
                        tA + swz128((uint32_t)((wm * 64 + mt * 16 + a_r) * 128 + (kk + a_c) * 2)));
#pragma unroll
            for (int mt = 0; mt < 4; mt++)
#pragma unroll
                for (int nt = 0; nt < 4; nt++)
                    mma_fp16(c[mt][nt], a + 4 * mt, bh + 2 * nt);
        }
        __syncthreads();
    }

    // ---- Epilogue: direct f32 stores + bias
#pragma unroll
    for (int mt = 0; mt < 4; mt++)
#pragma unroll
        for (int nt = 0; nt < 4; nt++) {
            int n = wn * 32 + nt * 8 + (lane & 3) * 2;
            float2 bv = *reinterpret_cast<const float2*>(&bias[n]);
#pragma unroll
            for (int h = 0; h < 2; h++) {
                int m = wm * 64 + mt * 16 + (lane >> 2) + h * 8;
                size_t ob = ((size_t)bi * L_SEQ + m) * KOUT + n;
                float2 v;
                v.x = c[mt][nt][2 * h]     + bv.x;
                v.y = c[mt][nt][2 * h + 1] + bv.y;
                *reinterpret_cast<float2*>(&out[ob]) = v;
            }
        }
}

// ---------------------------------------------------------------------------
// Launch
// ---------------------------------------------------------------------------
extern "C" void kernel_launch(void* const* d_in, const int* in_sizes, int n_in,
                              void* d_out, int out_size)
{
    const float* x1   = (const float*)d_in[0];   // [8,256,512]
    const float* x2   = (const float*)d_in[1];   // [8,256,512]
    const float* w    = (const float*)d_in[2];   // [64,512,512]
    const float* bias = (const float*)d_in[3];   // [64]
    float* out = (float*)d_out;                  // [8,256,256,64]

    cudaFuncSetAttribute(gemm1_mma, cudaFuncAttributeMaxDynamicSharedMemorySize, G1_SMEM);
    cudaFuncSetAttribute(gemm2_mma, cudaFuncAttributeMaxDynamicSharedMemorySize, G2_SMEM);

    int n4 = M1 * D1 / 4;
    cvt_fp16_kernel<<<(n4 + 255) / 256, 256>>>(x1, x2, n4);
    cvt_w_kernel<<<dim3(16, 16, 64), dim3(32, 8)>>>(w);

    gemm1_mma<<<dim3(16, 2, 64), 256, G1_SMEM>>>();
    gemm2_mma<<<2048, 256, G2_SMEM>>>(bias, out);
}